// round 13
// baseline (speedup 1.0000x reference)
#include <cuda_runtime.h>
#include <cuda_bf16.h>
#include <cstdint>

// ---------------------------------------------------------------------------
// LIF layer forward (sm_103 base ISA):
//   cur = x @ W^T + bias   (3-pass split-bf16 HMMA GEMM; A split fused in-kernel,
//                           B via ldmatrix.x4, 3-stage cp.async pipeline)
//   scan: v = d*v*(1-z) + (1-d)*(cur_t + z @ R^T);  z = (v >= 1)
// Scan chunk-parallelized on the no-spike linear path + exact sequential
// fallback per batch element if any v >= THR (flagged).
// GEMM is split into batch-aligned quarters; each quarter's scan chain runs
// on a second stream, overlapping the next quarter's GEMM (fork/join events).
// d_out = [outputs | statesV | statesZ]
// ---------------------------------------------------------------------------

#define IN_DIM  512
#define OUT_DIM 512
#define MAX_M   64000
#define MAX_B   128
#define CH      125
#define MAX_NCH 16

__device__ __nv_bfloat16 g_whi[(size_t)OUT_DIM * IN_DIM];
__device__ __nv_bfloat16 g_wlo[(size_t)OUT_DIM * IN_DIM];
__device__ float         g_RT [(size_t)OUT_DIM * OUT_DIM];
__device__ float         g_cur[(size_t)MAX_M * OUT_DIM];
__device__ float         g_csum  [(size_t)MAX_B * MAX_NCH * OUT_DIM];
__device__ float         g_vbound[(size_t)MAX_B * MAX_NCH * OUT_DIM];
__device__ int           g_flag[MAX_B];

// ======================= small prep kernels =================================
__global__ void convert_w_kernel(const float* __restrict__ w) {
    int i = blockIdx.x * blockDim.x + threadIdx.x;
    float4 v = ((const float4*)w)[i];
    float vv[4] = {v.x, v.y, v.z, v.w};
    __nv_bfloat16 h[4], l[4];
#pragma unroll
    for (int k = 0; k < 4; k++) {
        h[k] = __float2bfloat16_rn(vv[k]);
        l[k] = __float2bfloat16_rn(vv[k] - __bfloat162float(h[k]));
    }
    __nv_bfloat162* hi2 = (__nv_bfloat162*)g_whi;
    __nv_bfloat162* lo2 = (__nv_bfloat162*)g_wlo;
    hi2[i * 2]     = __halves2bfloat162(h[0], h[1]);
    hi2[i * 2 + 1] = __halves2bfloat162(h[2], h[3]);
    lo2[i * 2]     = __halves2bfloat162(l[0], l[1]);
    lo2[i * 2 + 1] = __halves2bfloat162(l[2], l[3]);
}

__global__ void transpose512_kernel(const float* __restrict__ R) {
    __shared__ float tile[32][33];
    int x = blockIdx.x * 32 + threadIdx.x;
    int y = blockIdx.y * 32 + threadIdx.y;
    tile[threadIdx.y][threadIdx.x] = R[y * OUT_DIM + x];
    __syncthreads();
    int xo = blockIdx.y * 32 + threadIdx.x;
    int yo = blockIdx.x * 32 + threadIdx.y;
    g_RT[yo * OUT_DIM + xo] = tile[threadIdx.x][threadIdx.y];
}

// ======================= HMMA GEMM ==========================================
#define A_STRIDE_F 68
#define A_PART_B   (128 * A_STRIDE_F * 4)       // 34816
#define B_STRIDE   72
#define B_ROW_B    (B_STRIDE * 2)               // 144
#define B_PART_B   (128 * B_ROW_B)              // 18432
#define STAGE_B    (A_PART_B + 2 * B_PART_B)    // 71680
#define NPIPE      3
#define SMEM_GEMM  (NPIPE * STAGE_B)            // 215040

__device__ __forceinline__ uint32_t smem_u32(const void* p) {
    uint32_t a;
    asm("{ .reg .u64 t; cvta.to.shared.u64 t, %1; cvt.u32.u64 %0, t; }"
        : "=r"(a) : "l"(p));
    return a;
}

__device__ __forceinline__ void cp16(void* dst, const void* src) {
    uint32_t d;
    asm("{ .reg .u64 t; cvta.to.shared.u64 t, %1; cvt.u32.u64 %0, t; }"
        : "=r"(d) : "l"(dst));
    asm volatile("cp.async.cg.shared.global [%0], [%1], 16;" :: "r"(d), "l"(src));
}

__device__ __forceinline__ void ldsm_x4(uint32_t* r, uint32_t addr) {
    asm volatile("ldmatrix.sync.aligned.m8n8.x4.shared.b16 {%0,%1,%2,%3}, [%4];"
        : "=r"(r[0]), "=r"(r[1]), "=r"(r[2]), "=r"(r[3]) : "r"(addr));
}

__device__ __forceinline__ void mma_bf16(float* d, const uint32_t* a,
                                         uint32_t b0, uint32_t b1) {
    asm volatile(
        "mma.sync.aligned.m16n8k16.row.col.f32.bf16.bf16.f32 "
        "{%0,%1,%2,%3}, {%4,%5,%6,%7}, {%8,%9}, {%0,%1,%2,%3};"
        : "+f"(d[0]), "+f"(d[1]), "+f"(d[2]), "+f"(d[3])
        : "r"(a[0]), "r"(a[1]), "r"(a[2]), "r"(a[3]), "r"(b0), "r"(b1));
}

__device__ __forceinline__ void split2(float2 f, uint32_t& h, uint32_t& l) {
    asm("cvt.rn.bf16x2.f32 %0, %1, %2;" : "=r"(h) : "f"(f.y), "f"(f.x));
    float h0 = __uint_as_float(h << 16);
    float h1 = __uint_as_float(h & 0xffff0000u);
    float l0 = f.x - h0;
    float l1 = f.y - h1;
    asm("cvt.rn.bf16x2.f32 %0, %1, %2;" : "=r"(l) : "f"(l1), "f"(l0));
}

__device__ __forceinline__ void load_stage(char* sm, int buf,
        const float* A, const __nv_bfloat16* Bh, const __nv_bfloat16* Bl,
        int k0, int tid) {
    char* base = sm + buf * STAGE_B;
    {
        const float* gp = A + k0;
#pragma unroll
        for (int it = 0; it < 8; it++) {
            int chunk = it * 256 + tid;
            int row = chunk >> 4;
            int cc  = chunk & 15;
            cp16(base + row * (A_STRIDE_F * 4) + cc * 16,
                 gp + (size_t)row * IN_DIM + cc * 4);
        }
    }
    const __nv_bfloat16* srcs[2] = {Bh, Bl};
#pragma unroll
    for (int p = 0; p < 2; p++) {
        char* pb = base + A_PART_B + p * B_PART_B;
        const __nv_bfloat16* gp = srcs[p] + k0;
#pragma unroll
        for (int it = 0; it < 4; it++) {
            int chunk = it * 256 + tid;
            int row = chunk >> 3;
            int cc  = chunk & 7;
            cp16(pb + row * B_ROW_B + cc * 16,
                 gp + (size_t)row * IN_DIM + cc * 8);
        }
    }
    asm volatile("cp.async.commit_group;");
}

__global__ __launch_bounds__(256)
void gemm_hmma_kernel(const float* __restrict__ x,
                      const float* __restrict__ bias,
                      float* __restrict__ C,
                      int m_base) {
    extern __shared__ char sm[];
    const uint32_t sbase = smem_u32(sm);
    const int tid  = threadIdx.x;
    const int wid  = tid >> 5;
    const int lane = tid & 31;
    const int g = lane >> 2, t = lane & 3;
    const int wm = wid >> 1;
    const int wn = wid & 1;
    const int m0 = m_base + blockIdx.x * 128;
    const int n0 = blockIdx.y * 128;

    const float*         A  = x     + (size_t)m0 * IN_DIM;
    const __nv_bfloat16* Bh = g_whi + (size_t)n0 * IN_DIM;
    const __nv_bfloat16* Bl = g_wlo + (size_t)n0 * IN_DIM;

    const uint32_t bRowOff = (uint32_t)(wn * 64 + (lane & 15)) * B_ROW_B
                           + (uint32_t)(lane >> 4) * 16;

    float d[2][8][4];
#pragma unroll
    for (int mi = 0; mi < 2; mi++)
#pragma unroll
        for (int nj = 0; nj < 8; nj++)
#pragma unroll
            for (int r = 0; r < 4; r++) d[mi][nj][r] = 0.f;

    load_stage(sm, 0, A, Bh, Bl, 0, tid);
    load_stage(sm, 1, A, Bh, Bl, 64, tid);

#pragma unroll 1
    for (int s = 0; s < 8; s++) {
        if (s < 7) {
            asm volatile("cp.async.wait_group 1;");
        } else {
            asm volatile("cp.async.wait_group 0;");
        }
        __syncthreads();

        if (s + 2 < 8)
            load_stage(sm, (s + 2) % NPIPE, A, Bh, Bl, (s + 2) * 64, tid);

        const int buf = s % NPIPE;
        const float* Af = (const float*)(sm + buf * STAGE_B);
        const uint32_t bHb = sbase + buf * STAGE_B + A_PART_B + bRowOff;
        const uint32_t bLb = bHb + B_PART_B;

#pragma unroll
        for (int kk = 0; kk < 4; kk++) {
            const int col = kk * 16 + 2 * t;
            uint32_t ah[2][4], al[2][4];
#pragma unroll
            for (int mi = 0; mi < 2; mi++) {
                int r0 = wm * 32 + mi * 16 + g;
                float2 f0 = *(const float2*)&Af[(size_t)r0 * A_STRIDE_F + col];
                float2 f1 = *(const float2*)&Af[(size_t)(r0 + 8) * A_STRIDE_F + col];
                float2 f2 = *(const float2*)&Af[(size_t)r0 * A_STRIDE_F + col + 8];
                float2 f3 = *(const float2*)&Af[(size_t)(r0 + 8) * A_STRIDE_F + col + 8];
                split2(f0, ah[mi][0], al[mi][0]);
                split2(f1, ah[mi][1], al[mi][1]);
                split2(f2, ah[mi][2], al[mi][2]);
                split2(f3, ah[mi][3], al[mi][3]);
            }
            uint32_t bh[8][2], bl[8][2];
#pragma unroll
            for (int p = 0; p < 4; p++) {
                uint32_t r[4];
                ldsm_x4(r, bHb + p * (16 * B_ROW_B) + kk * 32);
                bh[2 * p][0] = r[0]; bh[2 * p + 1][0] = r[1];
                bh[2 * p][1] = r[2]; bh[2 * p + 1][1] = r[3];
                ldsm_x4(r, bLb + p * (16 * B_ROW_B) + kk * 32);
                bl[2 * p][0] = r[0]; bl[2 * p + 1][0] = r[1];
                bl[2 * p][1] = r[2]; bl[2 * p + 1][1] = r[3];
            }
#pragma unroll
            for (int mi = 0; mi < 2; mi++)
#pragma unroll
                for (int nj = 0; nj < 8; nj++)
                    mma_bf16(d[mi][nj], ah[mi], bh[nj][0], bh[nj][1]);
#pragma unroll
            for (int mi = 0; mi < 2; mi++)
#pragma unroll
                for (int nj = 0; nj < 8; nj++)
                    mma_bf16(d[mi][nj], ah[mi], bl[nj][0], bl[nj][1]);
#pragma unroll
            for (int mi = 0; mi < 2; mi++)
#pragma unroll
                for (int nj = 0; nj < 8; nj++)
                    mma_bf16(d[mi][nj], al[mi], bh[nj][0], bh[nj][1]);
        }
    }

#pragma unroll
    for (int nj = 0; nj < 8; nj++) {
        int cc = n0 + wn * 64 + nj * 8 + 2 * t;
        float2 bv = *(const float2*)&bias[cc];
#pragma unroll
        for (int mi = 0; mi < 2; mi++) {
            int r0 = m0 + wm * 32 + mi * 16 + g;
            float2 o0 = {d[mi][nj][0] + bv.x, d[mi][nj][1] + bv.y};
            float2 o1 = {d[mi][nj][2] + bv.x, d[mi][nj][3] + bv.y};
            __stcs((float2*)&C[(size_t)r0 * OUT_DIM + cc], o0);
            __stcs((float2*)&C[(size_t)(r0 + 8) * OUT_DIM + cc], o1);
        }
    }
}

// ================= Parallel scan, stage 1: chunk-local EMA sums ==============
__global__ __launch_bounds__(OUT_DIM)
void scan_s1_kernel(const float* __restrict__ decay, int T, int NCH, int b0) {
    const int bc = blockIdx.x;
    const int b  = b0 + bc / NCH;
    const int ch = bc % NCH;
    const int o  = threadIdx.x;
    if (ch == 0 && o == 0) g_flag[b] = 0;

    const float d = decay[o];
    const float omd = 1.f - d;
    const int t0 = ch * CH;
    const int len = min(T - t0, CH);
    const float* curB = g_cur + ((size_t)b * T + t0) * OUT_DIM + o;

    float c0 = 0.f, c1 = 0.f, c2 = 0.f, c3 = 0.f;
    if (len > 0) c0 = __ldcs(curB);
    if (len > 1) c1 = __ldcs(curB + (size_t)OUT_DIM);
    if (len > 2) c2 = __ldcs(curB + (size_t)2 * OUT_DIM);
    if (len > 3) c3 = __ldcs(curB + (size_t)3 * OUT_DIM);

    float s = 0.f;
    int t = 0;
#pragma unroll 1
    for (; t + 4 <= len; t += 4) {
        float n0 = (t + 4 < len) ? __ldcs(curB + (size_t)(t + 4) * OUT_DIM) : 0.f;
        float n1 = (t + 5 < len) ? __ldcs(curB + (size_t)(t + 5) * OUT_DIM) : 0.f;
        float n2 = (t + 6 < len) ? __ldcs(curB + (size_t)(t + 6) * OUT_DIM) : 0.f;
        float n3 = (t + 7 < len) ? __ldcs(curB + (size_t)(t + 7) * OUT_DIM) : 0.f;
        s = d * s + omd * c0;
        s = d * s + omd * c1;
        s = d * s + omd * c2;
        s = d * s + omd * c3;
        c0 = n0; c1 = n1; c2 = n2; c3 = n3;
    }
    if (t < len) { s = d * s + omd * c0; t++; }
    if (t < len) { s = d * s + omd * c1; t++; }
    if (t < len) { s = d * s + omd * c2; t++; }

    g_csum[((size_t)b * NCH + ch) * OUT_DIM + o] = s;
}

// ================= stage 2: combine chunk boundaries ========================
__global__ __launch_bounds__(OUT_DIM)
void scan_s2_kernel(const float* __restrict__ decay, int T, int NCH, int b0) {
    const int b = b0 + blockIdx.x;
    const int o = threadIdx.x;
    const float d = decay[o];

    float dpCH = 1.f;
#pragma unroll 1
    for (int i = 0; i < CH; i++) dpCH *= d;

    float vb = 0.f;
#pragma unroll 1
    for (int ch = 0; ch < NCH; ch++) {
        g_vbound[((size_t)b * NCH + ch) * OUT_DIM + o] = vb;
        int len = min(CH, T - ch * CH);
        float dp = dpCH;
        if (len != CH) { dp = 1.f; for (int i = 0; i < len; i++) dp *= d; }
        vb = dp * vb + g_csum[((size_t)b * NCH + ch) * OUT_DIM + o];
    }
}

// ================= stage 3: expand no-spike trajectory + flag ================
__global__ __launch_bounds__(OUT_DIM)
void scan_s3_kernel(const float* __restrict__ decay, int T, int NCH, int b0,
                    float* __restrict__ outputs,
                    float* __restrict__ statesV,
                    float* __restrict__ statesZ) {
    const int bc = blockIdx.x;
    const int b  = b0 + bc / NCH;
    const int ch = bc % NCH;
    const int o  = threadIdx.x;

    const float d = decay[o];
    const float omd = 1.f - d;
    const int t0 = ch * CH;
    const int len = min(T - t0, CH);

    const float* curB = g_cur + ((size_t)b * T + t0) * OUT_DIM + o;
    float* outB = outputs + ((size_t)b * T + t0) * OUT_DIM + o;
    float* svB  = statesV + ((size_t)b * (T + 1) + t0 + 1) * OUT_DIM + o;
    float* szB  = statesZ + ((size_t)b * (T + 1) + t0 + 1) * OUT_DIM + o;

    if (ch == 0) {
        statesV[((size_t)b * (T + 1)) * OUT_DIM + o] = 0.f;
        statesZ[((size_t)b * (T + 1)) * OUT_DIM + o] = 0.f;
    }

    float c0 = 0.f, c1 = 0.f, c2 = 0.f, c3 = 0.f;
    if (len > 0) c0 = __ldcs(curB);
    if (len > 1) c1 = __ldcs(curB + (size_t)OUT_DIM);
    if (len > 2) c2 = __ldcs(curB + (size_t)2 * OUT_DIM);
    if (len > 3) c3 = __ldcs(curB + (size_t)3 * OUT_DIM);

    float v = g_vbound[((size_t)b * NCH + ch) * OUT_DIM + o];
    bool spike = false;
    int t = 0;
#pragma unroll 1
    for (; t + 4 <= len; t += 4) {
        float n0 = (t + 4 < len) ? __ldcs(curB + (size_t)(t + 4) * OUT_DIM) : 0.f;
        float n1 = (t + 5 < len) ? __ldcs(curB + (size_t)(t + 5) * OUT_DIM) : 0.f;
        float n2 = (t + 6 < len) ? __ldcs(curB + (size_t)(t + 6) * OUT_DIM) : 0.f;
        float n3 = (t + 7 < len) ? __ldcs(curB + (size_t)(t + 7) * OUT_DIM) : 0.f;
#pragma unroll
        for (int u = 0; u < 4; u++) {
            float cc = (u == 0) ? c0 : (u == 1) ? c1 : (u == 2) ? c2 : c3;
            v = d * v + omd * cc;
            float z = (v >= 1.f) ? 1.f : 0.f;
            spike |= (z > 0.f);
            size_t off = (size_t)(t + u) * OUT_DIM;
            __stcs(outB + off, z);
            __stcs(svB + off, v);
            __stcs(szB + off, z);
        }
        c0 = n0; c1 = n1; c2 = n2; c3 = n3;
    }
#pragma unroll 1
    for (int u = 0; t < len; t++, u++) {
        float cc = (u == 0) ? c0 : (u == 1) ? c1 : c2;
        v = d * v + omd * cc;
        float z = (v >= 1.f) ? 1.f : 0.f;
        spike |= (z > 0.f);
        size_t off = (size_t)t * OUT_DIM;
        __stcs(outB + off, z);
        __stcs(svB + off, v);
        __stcs(szB + off, z);
    }
    if (__syncthreads_or(spike)) {
        if (o == 0) atomicOr(&g_flag[b], 1);
    }
}

// ================= stage 4: exact sequential fallback (flagged only) ========
__device__ __forceinline__ void lif_step(
    float c, float& v, float& z, int& anySpike,
    unsigned* smask, int o, int wid, int lane,
    float d, float omd,
    float* __restrict__ outB, float* __restrict__ svB, float* __restrict__ szB,
    int t)
{
    float soma = c;
    if (anySpike) {
#pragma unroll 1
        for (int w = 0; w < OUT_DIM / 32; w++) {
            unsigned m = smask[w];
            while (m) {
                int j = w * 32 + (__ffs(m) - 1);
                m &= (m - 1);
                soma += g_RT[(size_t)j * OUT_DIM + o];
            }
        }
    }
    v = d * (v * (1.f - z)) + omd * soma;
    z = (v >= 1.f) ? 1.f : 0.f;
    outB[(size_t)t * OUT_DIM + o]      = z;
    svB[(size_t)(t + 1) * OUT_DIM + o] = v;
    szB[(size_t)(t + 1) * OUT_DIM + o] = z;
    unsigned bal = __ballot_sync(0xffffffffu, z > 0.f);
    anySpike = __syncthreads_count(z > 0.f);
    if (anySpike) {
        if (lane == 0) smask[wid] = bal;
        __syncthreads();
    }
}

__global__ __launch_bounds__(OUT_DIM, 1)
void scan_s4_kernel(const float* __restrict__ decay,
                    float* __restrict__ outputs,
                    float* __restrict__ statesV,
                    float* __restrict__ statesZ,
                    int T, int b0) {
    const int b = b0 + blockIdx.x;
    if (g_flag[b] == 0) return;
    const int o = threadIdx.x;
    const int wid = o >> 5, lane = o & 31;

    __shared__ unsigned smask[OUT_DIM / 32];
    if (o < OUT_DIM / 32) smask[o] = 0u;

    const float d   = decay[o];
    const float omd = 1.f - d;

    const float* curB = g_cur + (size_t)b * T * OUT_DIM;
    float* outB = outputs + (size_t)b * T * OUT_DIM;
    float* svB  = statesV + (size_t)b * (T + 1) * OUT_DIM;
    float* szB  = statesZ + (size_t)b * (T + 1) * OUT_DIM;

    svB[o] = 0.f;
    szB[o] = 0.f;

    float v = 0.f, z = 0.f;
    int anySpike = 0;
    __syncthreads();

    float c0 = 0.f, c1 = 0.f, c2 = 0.f, c3 = 0.f;
    if (T > 0) c0 = curB[o];
    if (T > 1) c1 = curB[(size_t)OUT_DIM + o];
    if (T > 2) c2 = curB[(size_t)2 * OUT_DIM + o];
    if (T > 3) c3 = curB[(size_t)3 * OUT_DIM + o];

    int t = 0;
#pragma unroll 1
    for (; t + 3 < T; t += 4) {
        float n0 = (t + 4 < T) ? curB[(size_t)(t + 4) * OUT_DIM + o] : 0.f;
        lif_step(c0, v, z, anySpike, smask, o, wid, lane, d, omd, outB, svB, szB, t);
        float n1 = (t + 5 < T) ? curB[(size_t)(t + 5) * OUT_DIM + o] : 0.f;
        lif_step(c1, v, z, anySpike, smask, o, wid, lane, d, omd, outB, svB, szB, t + 1);
        float n2 = (t + 6 < T) ? curB[(size_t)(t + 6) * OUT_DIM + o] : 0.f;
        lif_step(c2, v, z, anySpike, smask, o, wid, lane, d, omd, outB, svB, szB, t + 2);
        float n3 = (t + 7 < T) ? curB[(size_t)(t + 7) * OUT_DIM + o] : 0.f;
        lif_step(c3, v, z, anySpike, smask, o, wid, lane, d, omd, outB, svB, szB, t + 3);
        c0 = n0; c1 = n1; c2 = n2; c3 = n3;
    }
    if (t < T) { lif_step(c0, v, z, anySpike, smask, o, wid, lane, d, omd, outB, svB, szB, t); t++; }
    if (t < T) { lif_step(c1, v, z, anySpike, smask, o, wid, lane, d, omd, outB, svB, szB, t); t++; }
    if (t < T) { lif_step(c2, v, z, anySpike, smask, o, wid, lane, d, omd, outB, svB, szB, t); t++; }
}

// ---------------------------------------------------------------------------
extern "C" void kernel_launch(void* const* d_in, const int* in_sizes, int n_in,
                              void* d_out, int out_size) {
    const float* x      = (const float*)d_in[0];  // [B, T, IN]
    const float* weight = (const float*)d_in[1];  // [OUT, IN]
    const float* bias   = (const float*)d_in[2];  // [OUT]
    const float* recur  = (const float*)d_in[3];  // [OUT, OUT]
    const float* decay  = (const float*)d_in[4];  // [OUT]

    const int OUT = in_sizes[2];                         // 512
    const int IN  = in_sizes[1] / OUT;                   // 512
    const long long M = (long long)in_sizes[0] / IN;     // B*T
    const long long B = (((long long)out_size / OUT) - 3 * M) / 2;
    const int T = (int)(M / B);
    const int NCH = (T + CH - 1) / CH;

    float* outputs = (float*)d_out;                        // [B,T,OUT]
    float* statesV = outputs + (size_t)B * T * OUT;        // [B,T+1,OUT]
    float* statesZ = statesV + (size_t)B * (T + 1) * OUT;  // [B,T+1,OUT]

    float* cur;
    cudaGetSymbolAddress((void**)&cur, g_cur);

    // choose split so each GEMM slice ends on a batch boundary AND a 128-row
    // boundary
    int NSPLIT = 1;
    if (B % 4 == 0 && ((B / 4) * (long long)T) % 128 == 0) NSPLIT = 4;
    else if (B % 2 == 0 && ((B / 2) * (long long)T) % 128 == 0) NSPLIT = 2;

    // one-time stream/event setup (work per call is identical; failure
    // degrades to the serial default-stream path, still correct)
    static cudaStream_t s_scan = 0;
    static cudaEvent_t  s_ev[5];
    static bool s_init = false;
    if (!s_init) {
        if (cudaStreamCreateWithFlags(&s_scan, cudaStreamNonBlocking) != cudaSuccess)
            s_scan = 0;
        for (int i = 0; i < 5; i++)
            cudaEventCreateWithFlags(&s_ev[i], cudaEventDisableTiming);
        s_init = true;
    }
    const bool overlap = (NSPLIT > 1) && (s_scan != 0);

    convert_w_kernel<<<(OUT * IN / 4) / 256, 256>>>(weight);
    {
        dim3 grid(OUT / 32, OUT / 32), block(32, 32);
        transpose512_kernel<<<grid, block>>>(recur);
    }

    cudaFuncSetAttribute(gemm_hmma_kernel,
                         cudaFuncAttributeMaxDynamicSharedMemorySize, SMEM_GEMM);

    const int nsp   = overlap ? NSPLIT : 1;
    const int bPer  = (int)(B / nsp);
    const int mPer  = (int)(bPer * (long long)T);

    // GEMM slices on default stream (serial); record an event after each
    for (int sp = 0; sp < nsp; sp++) {
        dim3 grid(mPer / 128, OUT / 128);
        gemm_hmma_kernel<<<grid, 256, SMEM_GEMM>>>(x, bias, cur, sp * mPer);
        if (overlap) cudaEventRecord(s_ev[sp], 0);
    }

    // scan chains: slice sp on the scan stream, gated on its GEMM event
    for (int sp = 0; sp < nsp; sp++) {
        cudaStream_t st = overlap ? s_scan : (cudaStream_t)0;
        if (overlap) cudaStreamWaitEvent(st, s_ev[sp], 0);
        int b0 = sp * bPer;
        scan_s1_kernel<<<bPer * NCH, OUT, 0, st>>>(decay, T, NCH, b0);
        scan_s2_kernel<<<bPer, OUT, 0, st>>>(decay, T, NCH, b0);
        scan_s3_kernel<<<bPer * NCH, OUT, 0, st>>>(decay, T, NCH, b0,
                                                   outputs, statesV, statesZ);
        scan_s4_kernel<<<bPer, OUT, 0, st>>>(decay, outputs, statesV, statesZ,
                                             T, b0);
    }
    if (overlap) {
        cudaEventRecord(s_ev[4], s_scan);
        cudaStreamWaitEvent((cudaStream_t)0, s_ev[4], 0);   // join
    }
}

// round 14
// speedup vs baseline: 1.1568x; 1.1568x over previous
#include <cuda_runtime.h>
#include <cuda_bf16.h>
#include <cstdint>

// ---------------------------------------------------------------------------
// LIF layer forward (sm_103 base ISA):
//   cur = x @ W^T + bias   (3-pass split-bf16 HMMA GEMM; A split fused in-kernel,
//                           B via ldmatrix.x4, 3-stage cp.async pipeline,
//                           kk-fragments software-pipelined in registers)
//   scan: v = d*v*(1-z) + (1-d)*(cur_t + z @ R^T);  z = (v >= 1)
// Scan chunk-parallelized on the no-spike linear path + exact sequential
// fallback per batch element if any v >= THR (flagged).
// d_out = [outputs | statesV | statesZ]
// ---------------------------------------------------------------------------

#define IN_DIM  512
#define OUT_DIM 512
#define MAX_M   64000
#define MAX_B   128
#define CH      125
#define MAX_NCH 16

__device__ __nv_bfloat16 g_whi[(size_t)OUT_DIM * IN_DIM];
__device__ __nv_bfloat16 g_wlo[(size_t)OUT_DIM * IN_DIM];
__device__ float         g_RT [(size_t)OUT_DIM * OUT_DIM];
__device__ float         g_cur[(size_t)MAX_M * OUT_DIM];
__device__ float         g_csum  [(size_t)MAX_B * MAX_NCH * OUT_DIM];
__device__ float         g_vbound[(size_t)MAX_B * MAX_NCH * OUT_DIM];
__device__ int           g_flag[MAX_B];

// ======================= small prep kernels =================================
__global__ void convert_w_kernel(const float* __restrict__ w) {
    int i = blockIdx.x * blockDim.x + threadIdx.x;
    float4 v = ((const float4*)w)[i];
    float vv[4] = {v.x, v.y, v.z, v.w};
    __nv_bfloat16 h[4], l[4];
#pragma unroll
    for (int k = 0; k < 4; k++) {
        h[k] = __float2bfloat16_rn(vv[k]);
        l[k] = __float2bfloat16_rn(vv[k] - __bfloat162float(h[k]));
    }
    __nv_bfloat162* hi2 = (__nv_bfloat162*)g_whi;
    __nv_bfloat162* lo2 = (__nv_bfloat162*)g_wlo;
    hi2[i * 2]     = __halves2bfloat162(h[0], h[1]);
    hi2[i * 2 + 1] = __halves2bfloat162(h[2], h[3]);
    lo2[i * 2]     = __halves2bfloat162(l[0], l[1]);
    lo2[i * 2 + 1] = __halves2bfloat162(l[2], l[3]);
}

__global__ void transpose512_kernel(const float* __restrict__ R) {
    __shared__ float tile[32][33];
    int x = blockIdx.x * 32 + threadIdx.x;
    int y = blockIdx.y * 32 + threadIdx.y;
    tile[threadIdx.y][threadIdx.x] = R[y * OUT_DIM + x];
    __syncthreads();
    int xo = blockIdx.y * 32 + threadIdx.x;
    int yo = blockIdx.x * 32 + threadIdx.y;
    g_RT[yo * OUT_DIM + xo] = tile[threadIdx.x][threadIdx.y];
}

// ======================= HMMA GEMM ==========================================
#define A_STRIDE_F 68
#define A_PART_B   (128 * A_STRIDE_F * 4)       // 34816
#define B_STRIDE   72
#define B_ROW_B    (B_STRIDE * 2)               // 144
#define B_PART_B   (128 * B_ROW_B)              // 18432
#define STAGE_B    (A_PART_B + 2 * B_PART_B)    // 71680
#define NPIPE      3
#define SMEM_GEMM  (NPIPE * STAGE_B)            // 215040

__device__ __forceinline__ uint32_t smem_u32(const void* p) {
    uint32_t a;
    asm("{ .reg .u64 t; cvta.to.shared.u64 t, %1; cvt.u32.u64 %0, t; }"
        : "=r"(a) : "l"(p));
    return a;
}

__device__ __forceinline__ void cp16(void* dst, const void* src) {
    uint32_t d;
    asm("{ .reg .u64 t; cvta.to.shared.u64 t, %1; cvt.u32.u64 %0, t; }"
        : "=r"(d) : "l"(dst));
    asm volatile("cp.async.cg.shared.global [%0], [%1], 16;" :: "r"(d), "l"(src));
}

__device__ __forceinline__ void ldsm_x4(uint32_t* r, uint32_t addr) {
    asm volatile("ldmatrix.sync.aligned.m8n8.x4.shared.b16 {%0,%1,%2,%3}, [%4];"
        : "=r"(r[0]), "=r"(r[1]), "=r"(r[2]), "=r"(r[3]) : "r"(addr));
}

__device__ __forceinline__ void mma_bf16(float* d, const uint32_t* a,
                                         uint32_t b0, uint32_t b1) {
    asm volatile(
        "mma.sync.aligned.m16n8k16.row.col.f32.bf16.bf16.f32 "
        "{%0,%1,%2,%3}, {%4,%5,%6,%7}, {%8,%9}, {%0,%1,%2,%3};"
        : "+f"(d[0]), "+f"(d[1]), "+f"(d[2]), "+f"(d[3])
        : "r"(a[0]), "r"(a[1]), "r"(a[2]), "r"(a[3]), "r"(b0), "r"(b1));
}

__device__ __forceinline__ void split2(float2 f, uint32_t& h, uint32_t& l) {
    asm("cvt.rn.bf16x2.f32 %0, %1, %2;" : "=r"(h) : "f"(f.y), "f"(f.x));
    float h0 = __uint_as_float(h << 16);
    float h1 = __uint_as_float(h & 0xffff0000u);
    float l0 = f.x - h0;
    float l1 = f.y - h1;
    asm("cvt.rn.bf16x2.f32 %0, %1, %2;" : "=r"(l) : "f"(l1), "f"(l0));
}

struct Frag {
    uint32_t ah[2][4], al[2][4];
    uint32_t bh[8][2], bl[8][2];
};

// Load + split all fragments for one kk slice.
__device__ __forceinline__ void frag_load(Frag& F, const float* Af,
                                          uint32_t bHb, uint32_t bLb,
                                          int kk, int wm, int g, int t) {
    const int col = kk * 16 + 2 * t;
#pragma unroll
    for (int mi = 0; mi < 2; mi++) {
        int r0 = wm * 32 + mi * 16 + g;
        float2 f0 = *(const float2*)&Af[(size_t)r0 * A_STRIDE_F + col];
        float2 f1 = *(const float2*)&Af[(size_t)(r0 + 8) * A_STRIDE_F + col];
        float2 f2 = *(const float2*)&Af[(size_t)r0 * A_STRIDE_F + col + 8];
        float2 f3 = *(const float2*)&Af[(size_t)(r0 + 8) * A_STRIDE_F + col + 8];
        split2(f0, F.ah[mi][0], F.al[mi][0]);
        split2(f1, F.ah[mi][1], F.al[mi][1]);
        split2(f2, F.ah[mi][2], F.al[mi][2]);
        split2(f3, F.ah[mi][3], F.al[mi][3]);
    }
#pragma unroll
    for (int p = 0; p < 4; p++) {
        uint32_t r[4];
        ldsm_x4(r, bHb + p * (16 * B_ROW_B) + kk * 32);
        F.bh[2 * p][0] = r[0]; F.bh[2 * p + 1][0] = r[1];
        F.bh[2 * p][1] = r[2]; F.bh[2 * p + 1][1] = r[3];
        ldsm_x4(r, bLb + p * (16 * B_ROW_B) + kk * 32);
        F.bl[2 * p][0] = r[0]; F.bl[2 * p + 1][0] = r[1];
        F.bl[2 * p][1] = r[2]; F.bl[2 * p + 1][1] = r[3];
    }
}

__device__ __forceinline__ void frag_mma(float d[2][8][4], const Frag& F) {
#pragma unroll
    for (int mi = 0; mi < 2; mi++)
#pragma unroll
        for (int nj = 0; nj < 8; nj++)
            mma_bf16(d[mi][nj], F.ah[mi], F.bh[nj][0], F.bh[nj][1]);
#pragma unroll
    for (int mi = 0; mi < 2; mi++)
#pragma unroll
        for (int nj = 0; nj < 8; nj++)
            mma_bf16(d[mi][nj], F.ah[mi], F.bl[nj][0], F.bl[nj][1]);
#pragma unroll
    for (int mi = 0; mi < 2; mi++)
#pragma unroll
        for (int nj = 0; nj < 8; nj++)
            mma_bf16(d[mi][nj], F.al[mi], F.bh[nj][0], F.bh[nj][1]);
}

__device__ __forceinline__ void load_stage(char* sm, int buf,
        const float* A, const __nv_bfloat16* Bh, const __nv_bfloat16* Bl,
        int k0, int tid) {
    char* base = sm + buf * STAGE_B;
    {
        const float* gp = A + k0;
#pragma unroll
        for (int it = 0; it < 8; it++) {
            int chunk = it * 256 + tid;
            int row = chunk >> 4;
            int cc  = chunk & 15;
            cp16(base + row * (A_STRIDE_F * 4) + cc * 16,
                 gp + (size_t)row * IN_DIM + cc * 4);
        }
    }
    const __nv_bfloat16* srcs[2] = {Bh, Bl};
#pragma unroll
    for (int p = 0; p < 2; p++) {
        char* pb = base + A_PART_B + p * B_PART_B;
        const __nv_bfloat16* gp = srcs[p] + k0;
#pragma unroll
        for (int it = 0; it < 4; it++) {
            int chunk = it * 256 + tid;
            int row = chunk >> 3;
            int cc  = chunk & 7;
            cp16(pb + row * B_ROW_B + cc * 16,
                 gp + (size_t)row * IN_DIM + cc * 8);
        }
    }
    asm volatile("cp.async.commit_group;");
}

__global__ __launch_bounds__(256)
void gemm_hmma_kernel(const float* __restrict__ x,
                      const float* __restrict__ bias,
                      float* __restrict__ C) {
    extern __shared__ char sm[];
    const uint32_t sbase = smem_u32(sm);
    const int tid  = threadIdx.x;
    const int wid  = tid >> 5;
    const int lane = tid & 31;
    const int g = lane >> 2, t = lane & 3;
    const int wm = wid >> 1;
    const int wn = wid & 1;
    const int m0 = blockIdx.x * 128;
    const int n0 = blockIdx.y * 128;

    const float*         A  = x     + (size_t)m0 * IN_DIM;
    const __nv_bfloat16* Bh = g_whi + (size_t)n0 * IN_DIM;
    const __nv_bfloat16* Bl = g_wlo + (size_t)n0 * IN_DIM;

    const uint32_t bRowOff = (uint32_t)(wn * 64 + (lane & 15)) * B_ROW_B
                           + (uint32_t)(lane >> 4) * 16;

    float d[2][8][4];
#pragma unroll
    for (int mi = 0; mi < 2; mi++)
#pragma unroll
        for (int nj = 0; nj < 8; nj++)
#pragma unroll
            for (int r = 0; r < 4; r++) d[mi][nj][r] = 0.f;

    load_stage(sm, 0, A, Bh, Bl, 0, tid);
    load_stage(sm, 1, A, Bh, Bl, 64, tid);

    Frag Fa, Fb;

#pragma unroll 1
    for (int s = 0; s < 8; s++) {
        if (s < 7) {
            asm volatile("cp.async.wait_group 1;");
        } else {
            asm volatile("cp.async.wait_group 0;");
        }
        __syncthreads();

        if (s + 2 < 8)
            load_stage(sm, (s + 2) % NPIPE, A, Bh, Bl, (s + 2) * 64, tid);

        const int buf = s % NPIPE;
        const float* Af = (const float*)(sm + buf * STAGE_B);
        const uint32_t bHb = sbase + buf * STAGE_B + A_PART_B + bRowOff;
        const uint32_t bLb = bHb + B_PART_B;

        // kk fragment pipeline: load kk+1 before consuming kk
        frag_load(Fa, Af, bHb, bLb, 0, wm, g, t);
        frag_load(Fb, Af, bHb, bLb, 1, wm, g, t);
        frag_mma(d, Fa);
        frag_load(Fa, Af, bHb, bLb, 2, wm, g, t);
        frag_mma(d, Fb);
        frag_load(Fb, Af, bHb, bLb, 3, wm, g, t);
        frag_mma(d, Fa);
        frag_mma(d, Fb);
    }

#pragma unroll
    for (int nj = 0; nj < 8; nj++) {
        int cc = n0 + wn * 64 + nj * 8 + 2 * t;
        float2 bv = *(const float2*)&bias[cc];
#pragma unroll
        for (int mi = 0; mi < 2; mi++) {
            int r0 = m0 + wm * 32 + mi * 16 + g;
            float2 o0 = {d[mi][nj][0] + bv.x, d[mi][nj][1] + bv.y};
            float2 o1 = {d[mi][nj][2] + bv.x, d[mi][nj][3] + bv.y};
            __stcs((float2*)&C[(size_t)r0 * OUT_DIM + cc], o0);
            __stcs((float2*)&C[(size_t)(r0 + 8) * OUT_DIM + cc], o1);
        }
    }
}

// ================= Parallel scan, stage 1: chunk-local EMA sums ==============
__global__ __launch_bounds__(OUT_DIM)
void scan_s1_kernel(const float* __restrict__ decay, int T, int NCH) {
    const int bc = blockIdx.x;
    const int b  = bc / NCH;
    const int ch = bc % NCH;
    const int o  = threadIdx.x;
    if (ch == 0 && o == 0) g_flag[b] = 0;

    const float d = decay[o];
    const float omd = 1.f - d;
    const int t0 = ch * CH;
    const int len = min(T - t0, CH);
    const float* curB = g_cur + ((size_t)b * T + t0) * OUT_DIM + o;

    float c0 = 0.f, c1 = 0.f, c2 = 0.f, c3 = 0.f;
    if (len > 0) c0 = __ldcs(curB);
    if (len > 1) c1 = __ldcs(curB + (size_t)OUT_DIM);
    if (len > 2) c2 = __ldcs(curB + (size_t)2 * OUT_DIM);
    if (len > 3) c3 = __ldcs(curB + (size_t)3 * OUT_DIM);

    float s = 0.f;
    int t = 0;
#pragma unroll 1
    for (; t + 4 <= len; t += 4) {
        float n0 = (t + 4 < len) ? __ldcs(curB + (size_t)(t + 4) * OUT_DIM) : 0.f;
        float n1 = (t + 5 < len) ? __ldcs(curB + (size_t)(t + 5) * OUT_DIM) : 0.f;
        float n2 = (t + 6 < len) ? __ldcs(curB + (size_t)(t + 6) * OUT_DIM) : 0.f;
        float n3 = (t + 7 < len) ? __ldcs(curB + (size_t)(t + 7) * OUT_DIM) : 0.f;
        s = d * s + omd * c0;
        s = d * s + omd * c1;
        s = d * s + omd * c2;
        s = d * s + omd * c3;
        c0 = n0; c1 = n1; c2 = n2; c3 = n3;
    }
    if (t < len) { s = d * s + omd * c0; t++; }
    if (t < len) { s = d * s + omd * c1; t++; }
    if (t < len) { s = d * s + omd * c2; t++; }

    g_csum[(size_t)bc * OUT_DIM + o] = s;
}

// ================= stage 2: combine chunk boundaries ========================
__global__ __launch_bounds__(OUT_DIM)
void scan_s2_kernel(const float* __restrict__ decay, int T, int NCH) {
    const int b = blockIdx.x;
    const int o = threadIdx.x;
    const float d = decay[o];

    float dpCH = 1.f;
#pragma unroll 1
    for (int i = 0; i < CH; i++) dpCH *= d;

    float vb = 0.f;
#pragma unroll 1
    for (int ch = 0; ch < NCH; ch++) {
        g_vbound[((size_t)b * NCH + ch) * OUT_DIM + o] = vb;
        int len = min(CH, T - ch * CH);
        float dp = dpCH;
        if (len != CH) { dp = 1.f; for (int i = 0; i < len; i++) dp *= d; }
        vb = dp * vb + g_csum[((size_t)b * NCH + ch) * OUT_DIM + o];
    }
}

// ================= stage 3: expand no-spike trajectory + flag ================
__global__ __launch_bounds__(OUT_DIM)
void scan_s3_kernel(const float* __restrict__ decay, int T, int NCH,
                    float* __restrict__ outputs,
                    float* __restrict__ statesV,
                    float* __restrict__ statesZ) {
    const int bc = blockIdx.x;
    const int b  = bc / NCH;
    const int ch = bc % NCH;
    const int o  = threadIdx.x;

    const float d = decay[o];
    const float omd = 1.f - d;
    const int t0 = ch * CH;
    const int len = min(T - t0, CH);

    const float* curB = g_cur + ((size_t)b * T + t0) * OUT_DIM + o;
    float* outB = outputs + ((size_t)b * T + t0) * OUT_DIM + o;
    float* svB  = statesV + ((size_t)b * (T + 1) + t0 + 1) * OUT_DIM + o;
    float* szB  = statesZ + ((size_t)b * (T + 1) + t0 + 1) * OUT_DIM + o;

    if (ch == 0) {
        statesV[((size_t)b * (T + 1)) * OUT_DIM + o] = 0.f;
        statesZ[((size_t)b * (T + 1)) * OUT_DIM + o] = 0.f;
    }

    float c0 = 0.f, c1 = 0.f, c2 = 0.f, c3 = 0.f;
    if (len > 0) c0 = __ldcs(curB);
    if (len > 1) c1 = __ldcs(curB + (size_t)OUT_DIM);
    if (len > 2) c2 = __ldcs(curB + (size_t)2 * OUT_DIM);
    if (len > 3) c3 = __ldcs(curB + (size_t)3 * OUT_DIM);

    float v = g_vbound[(size_t)bc * OUT_DIM + o];
    bool spike = false;
    int t = 0;
#pragma unroll 1
    for (; t + 4 <= len; t += 4) {
        float n0 = (t + 4 < len) ? __ldcs(curB + (size_t)(t + 4) * OUT_DIM) : 0.f;
        float n1 = (t + 5 < len) ? __ldcs(curB + (size_t)(t + 5) * OUT_DIM) : 0.f;
        float n2 = (t + 6 < len) ? __ldcs(curB + (size_t)(t + 6) * OUT_DIM) : 0.f;
        float n3 = (t + 7 < len) ? __ldcs(curB + (size_t)(t + 7) * OUT_DIM) : 0.f;
#pragma unroll
        for (int u = 0; u < 4; u++) {
            float cc = (u == 0) ? c0 : (u == 1) ? c1 : (u == 2) ? c2 : c3;
            v = d * v + omd * cc;
            float z = (v >= 1.f) ? 1.f : 0.f;
            spike |= (z > 0.f);
            size_t off = (size_t)(t + u) * OUT_DIM;
            __stcs(outB + off, z);
            __stcs(svB + off, v);
            __stcs(szB + off, z);
        }
        c0 = n0; c1 = n1; c2 = n2; c3 = n3;
    }
#pragma unroll 1
    for (int u = 0; t < len; t++, u++) {
        float cc = (u == 0) ? c0 : (u == 1) ? c1 : c2;
        v = d * v + omd * cc;
        float z = (v >= 1.f) ? 1.f : 0.f;
        spike |= (z > 0.f);
        size_t off = (size_t)t * OUT_DIM;
        __stcs(outB + off, z);
        __stcs(svB + off, v);
        __stcs(szB + off, z);
    }
    if (__syncthreads_or(spike)) {
        if (o == 0) atomicOr(&g_flag[b], 1);
    }
}

// ================= stage 4: exact sequential fallback (flagged only) ========
__device__ __forceinline__ void lif_step(
    float c, float& v, float& z, int& anySpike,
    unsigned* smask, int o, int wid, int lane,
    float d, float omd,
    float* __restrict__ outB, float* __restrict__ svB, float* __restrict__ szB,
    int t)
{
    float soma = c;
    if (anySpike) {
#pragma unroll 1
        for (int w = 0; w < OUT_DIM / 32; w++) {
            unsigned m = smask[w];
            while (m) {
                int j = w * 32 + (__ffs(m) - 1);
                m &= (m - 1);
                soma += g_RT[(size_t)j * OUT_DIM + o];
            }
        }
    }
    v = d * (v * (1.f - z)) + omd * soma;
    z = (v >= 1.f) ? 1.f : 0.f;
    outB[(size_t)t * OUT_DIM + o]      = z;
    svB[(size_t)(t + 1) * OUT_DIM + o] = v;
    szB[(size_t)(t + 1) * OUT_DIM + o] = z;
    unsigned bal = __ballot_sync(0xffffffffu, z > 0.f);
    anySpike = __syncthreads_count(z > 0.f);
    if (anySpike) {
        if (lane == 0) smask[wid] = bal;
        __syncthreads();
    }
}

__global__ __launch_bounds__(OUT_DIM, 1)
void scan_s4_kernel(const float* __restrict__ decay,
                    float* __restrict__ outputs,
                    float* __restrict__ statesV,
                    float* __restrict__ statesZ,
                    int T) {
    const int b = blockIdx.x;
    if (g_flag[b] == 0) return;
    const int o = threadIdx.x;
    const int wid = o >> 5, lane = o & 31;

    __shared__ unsigned smask[OUT_DIM / 32];
    if (o < OUT_DIM / 32) smask[o] = 0u;

    const float d   = decay[o];
    const float omd = 1.f - d;

    const float* curB = g_cur + (size_t)b * T * OUT_DIM;
    float* outB = outputs + (size_t)b * T * OUT_DIM;
    float* svB  = statesV + (size_t)b * (T + 1) * OUT_DIM;
    float* szB  = statesZ + (size_t)b * (T + 1) * OUT_DIM;

    svB[o] = 0.f;
    szB[o] = 0.f;

    float v = 0.f, z = 0.f;
    int anySpike = 0;
    __syncthreads();

    float c0 = 0.f, c1 = 0.f, c2 = 0.f, c3 = 0.f;
    if (T > 0) c0 = curB[o];
    if (T > 1) c1 = curB[(size_t)OUT_DIM + o];
    if (T > 2) c2 = curB[(size_t)2 * OUT_DIM + o];
    if (T > 3) c3 = curB[(size_t)3 * OUT_DIM + o];

    int t = 0;
#pragma unroll 1
    for (; t + 3 < T; t += 4) {
        float n0 = (t + 4 < T) ? curB[(size_t)(t + 4) * OUT_DIM + o] : 0.f;
        lif_step(c0, v, z, anySpike, smask, o, wid, lane, d, omd, outB, svB, szB, t);
        float n1 = (t + 5 < T) ? curB[(size_t)(t + 5) * OUT_DIM + o] : 0.f;
        lif_step(c1, v, z, anySpike, smask, o, wid, lane, d, omd, outB, svB, szB, t + 1);
        float n2 = (t + 6 < T) ? curB[(size_t)(t + 6) * OUT_DIM + o] : 0.f;
        lif_step(c2, v, z, anySpike, smask, o, wid, lane, d, omd, outB, svB, szB, t + 2);
        float n3 = (t + 7 < T) ? curB[(size_t)(t + 7) * OUT_DIM + o] : 0.f;
        lif_step(c3, v, z, anySpike, smask, o, wid, lane, d, omd, outB, svB, szB, t + 3);
        c0 = n0; c1 = n1; c2 = n2; c3 = n3;
    }
    if (t < T) { lif_step(c0, v, z, anySpike, smask, o, wid, lane, d, omd, outB, svB, szB, t); t++; }
    if (t < T) { lif_step(c1, v, z, anySpike, smask, o, wid, lane, d, omd, outB, svB, szB, t); t++; }
    if (t < T) { lif_step(c2, v, z, anySpike, smask, o, wid, lane, d, omd, outB, svB, szB, t); t++; }
}

// ---------------------------------------------------------------------------
extern "C" void kernel_launch(void* const* d_in, const int* in_sizes, int n_in,
                              void* d_out, int out_size) {
    const float* x      = (const float*)d_in[0];  // [B, T, IN]
    const float* weight = (const float*)d_in[1];  // [OUT, IN]
    const float* bias   = (const float*)d_in[2];  // [OUT]
    const float* recur  = (const float*)d_in[3];  // [OUT, OUT]
    const float* decay  = (const float*)d_in[4];  // [OUT]

    const int OUT = in_sizes[2];                         // 512
    const int IN  = in_sizes[1] / OUT;                   // 512
    const long long M = (long long)in_sizes[0] / IN;     // B*T
    const long long B = (((long long)out_size / OUT) - 3 * M) / 2;
    const int T = (int)(M / B);
    const int NCH = (T + CH - 1) / CH;

    float* outputs = (float*)d_out;                        // [B,T,OUT]
    float* statesV = outputs + (size_t)B * T * OUT;        // [B,T+1,OUT]
    float* statesZ = statesV + (size_t)B * (T + 1) * OUT;  // [B,T+1,OUT]

    float* cur;
    cudaGetSymbolAddress((void**)&cur, g_cur);

    convert_w_kernel<<<(OUT * IN / 4) / 256, 256>>>(weight);
    {
        dim3 grid(OUT / 32, OUT / 32), block(32, 32);
        transpose512_kernel<<<grid, block>>>(recur);
    }

    cudaFuncSetAttribute(gemm_hmma_kernel,
                         cudaFuncAttributeMaxDynamicSharedMemorySize, SMEM_GEMM);
    {
        dim3 grid((unsigned)(M / 128), OUT / 128);
        gemm_hmma_kernel<<<grid, 256, SMEM_GEMM>>>(x, bias, cur);
    }

    scan_s1_kernel<<<(unsigned)(B * NCH), OUT>>>(decay, T, NCH);
    scan_s2_kernel<<<(unsigned)B, OUT>>>(decay, T, NCH);
    scan_s3_kernel<<<(unsigned)(B * NCH), OUT>>>(decay, T, NCH,
                                                 outputs, statesV, statesZ);
    scan_s4_kernel<<<(unsigned)B, OUT>>>(decay, outputs, statesV, statesZ, T);
}

// round 15
// speedup vs baseline: 1.2045x; 1.0412x over previous
#include <cuda_runtime.h>
#include <cuda_bf16.h>
#include <cstdint>

// ---------------------------------------------------------------------------
// LIF layer forward (sm_103 base ISA):
//   cur = x @ W^T + bias   (3-pass split-bf16 HMMA GEMM; A split fused in-kernel,
//                           B via ldmatrix.x4, 3-stage cp.async pipeline)
//   scan: v = d*v*(1-z) + (1-d)*(cur_t + z @ R^T);  z = (v >= 1)
// Scan chunk-parallelized on the no-spike linear path + exact sequential
// fallback per batch element if any v >= THR (flagged).
// d_out = [outputs | statesV | statesZ]
// ---------------------------------------------------------------------------

#define IN_DIM  512
#define OUT_DIM 512
#define MAX_M   64000
#define MAX_B   128
#define CH      125
#define MAX_NCH 16

__device__ __nv_bfloat16 g_whi[(size_t)OUT_DIM * IN_DIM];
__device__ __nv_bfloat16 g_wlo[(size_t)OUT_DIM * IN_DIM];
__device__ float         g_RT [(size_t)OUT_DIM * OUT_DIM];
__device__ float         g_cur[(size_t)MAX_M * OUT_DIM];
__device__ float         g_csum  [(size_t)MAX_B * MAX_NCH * OUT_DIM];
__device__ float         g_vbound[(size_t)MAX_B * MAX_NCH * OUT_DIM];
__device__ int           g_flag[MAX_B];

// ======================= small prep kernels =================================
__global__ void convert_w_kernel(const float* __restrict__ w) {
    int i = blockIdx.x * blockDim.x + threadIdx.x;
    float4 v = ((const float4*)w)[i];
    float vv[4] = {v.x, v.y, v.z, v.w};
    __nv_bfloat16 h[4], l[4];
#pragma unroll
    for (int k = 0; k < 4; k++) {
        h[k] = __float2bfloat16_rn(vv[k]);
        l[k] = __float2bfloat16_rn(vv[k] - __bfloat162float(h[k]));
    }
    __nv_bfloat162* hi2 = (__nv_bfloat162*)g_whi;
    __nv_bfloat162* lo2 = (__nv_bfloat162*)g_wlo;
    hi2[i * 2]     = __halves2bfloat162(h[0], h[1]);
    hi2[i * 2 + 1] = __halves2bfloat162(h[2], h[3]);
    lo2[i * 2]     = __halves2bfloat162(l[0], l[1]);
    lo2[i * 2 + 1] = __halves2bfloat162(l[2], l[3]);
}

__global__ void transpose512_kernel(const float* __restrict__ R) {
    __shared__ float tile[32][33];
    int x = blockIdx.x * 32 + threadIdx.x;
    int y = blockIdx.y * 32 + threadIdx.y;
    tile[threadIdx.y][threadIdx.x] = R[y * OUT_DIM + x];
    __syncthreads();
    int xo = blockIdx.y * 32 + threadIdx.x;
    int yo = blockIdx.x * 32 + threadIdx.y;
    g_RT[yo * OUT_DIM + xo] = tile[threadIdx.x][threadIdx.y];
}

// ======================= HMMA GEMM (R12-proven config) ======================
#define A_STRIDE_F 68
#define A_PART_B   (128 * A_STRIDE_F * 4)       // 34816
#define B_STRIDE   72
#define B_ROW_B    (B_STRIDE * 2)               // 144
#define B_PART_B   (128 * B_ROW_B)              // 18432
#define STAGE_B    (A_PART_B + 2 * B_PART_B)    // 71680
#define NPIPE      3
#define SMEM_GEMM  (NPIPE * STAGE_B)            // 215040

__device__ __forceinline__ uint32_t smem_u32(const void* p) {
    uint32_t a;
    asm("{ .reg .u64 t; cvta.to.shared.u64 t, %1; cvt.u32.u64 %0, t; }"
        : "=r"(a) : "l"(p));
    return a;
}

__device__ __forceinline__ void cp16(void* dst, const void* src) {
    uint32_t d;
    asm("{ .reg .u64 t; cvta.to.shared.u64 t, %1; cvt.u32.u64 %0, t; }"
        : "=r"(d) : "l"(dst));
    asm volatile("cp.async.cg.shared.global [%0], [%1], 16;" :: "r"(d), "l"(src));
}

__device__ __forceinline__ void ldsm_x4(uint32_t* r, uint32_t addr) {
    asm volatile("ldmatrix.sync.aligned.m8n8.x4.shared.b16 {%0,%1,%2,%3}, [%4];"
        : "=r"(r[0]), "=r"(r[1]), "=r"(r[2]), "=r"(r[3]) : "r"(addr));
}

__device__ __forceinline__ void mma_bf16(float* d, const uint32_t* a,
                                         uint32_t b0, uint32_t b1) {
    asm volatile(
        "mma.sync.aligned.m16n8k16.row.col.f32.bf16.bf16.f32 "
        "{%0,%1,%2,%3}, {%4,%5,%6,%7}, {%8,%9}, {%0,%1,%2,%3};"
        : "+f"(d[0]), "+f"(d[1]), "+f"(d[2]), "+f"(d[3])
        : "r"(a[0]), "r"(a[1]), "r"(a[2]), "r"(a[3]), "r"(b0), "r"(b1));
}

__device__ __forceinline__ void split2(float2 f, uint32_t& h, uint32_t& l) {
    asm("cvt.rn.bf16x2.f32 %0, %1, %2;" : "=r"(h) : "f"(f.y), "f"(f.x));
    float h0 = __uint_as_float(h << 16);
    float h1 = __uint_as_float(h & 0xffff0000u);
    float l0 = f.x - h0;
    float l1 = f.y - h1;
    asm("cvt.rn.bf16x2.f32 %0, %1, %2;" : "=r"(l) : "f"(l1), "f"(l0));
}

__device__ __forceinline__ void load_stage(char* sm, int buf,
        const float* A, const __nv_bfloat16* Bh, const __nv_bfloat16* Bl,
        int k0, int tid) {
    char* base = sm + buf * STAGE_B;
    {
        const float* gp = A + k0;
#pragma unroll
        for (int it = 0; it < 8; it++) {
            int chunk = it * 256 + tid;
            int row = chunk >> 4;
            int cc  = chunk & 15;
            cp16(base + row * (A_STRIDE_F * 4) + cc * 16,
                 gp + (size_t)row * IN_DIM + cc * 4);
        }
    }
    const __nv_bfloat16* srcs[2] = {Bh, Bl};
#pragma unroll
    for (int p = 0; p < 2; p++) {
        char* pb = base + A_PART_B + p * B_PART_B;
        const __nv_bfloat16* gp = srcs[p] + k0;
#pragma unroll
        for (int it = 0; it < 4; it++) {
            int chunk = it * 256 + tid;
            int row = chunk >> 3;
            int cc  = chunk & 7;
            cp16(pb + row * B_ROW_B + cc * 16,
                 gp + (size_t)row * IN_DIM + cc * 8);
        }
    }
    asm volatile("cp.async.commit_group;");
}

__global__ __launch_bounds__(256)
void gemm_hmma_kernel(const float* __restrict__ x,
                      const float* __restrict__ bias,
                      float* __restrict__ C) {
    extern __shared__ char sm[];
    const uint32_t sbase = smem_u32(sm);
    const int tid  = threadIdx.x;
    const int wid  = tid >> 5;
    const int lane = tid & 31;
    const int g = lane >> 2, t = lane & 3;
    const int wm = wid >> 1;
    const int wn = wid & 1;
    const int m0 = blockIdx.x * 128;
    const int n0 = blockIdx.y * 128;

    const float*         A  = x     + (size_t)m0 * IN_DIM;
    const __nv_bfloat16* Bh = g_whi + (size_t)n0 * IN_DIM;
    const __nv_bfloat16* Bl = g_wlo + (size_t)n0 * IN_DIM;

    const uint32_t bRowOff = (uint32_t)(wn * 64 + (lane & 15)) * B_ROW_B
                           + (uint32_t)(lane >> 4) * 16;

    float d[2][8][4];
#pragma unroll
    for (int mi = 0; mi < 2; mi++)
#pragma unroll
        for (int nj = 0; nj < 8; nj++)
#pragma unroll
            for (int r = 0; r < 4; r++) d[mi][nj][r] = 0.f;

    load_stage(sm, 0, A, Bh, Bl, 0, tid);
    load_stage(sm, 1, A, Bh, Bl, 64, tid);

#pragma unroll 1
    for (int s = 0; s < 8; s++) {
        if (s < 7) {
            asm volatile("cp.async.wait_group 1;");
        } else {
            asm volatile("cp.async.wait_group 0;");
        }
        __syncthreads();

        if (s + 2 < 8)
            load_stage(sm, (s + 2) % NPIPE, A, Bh, Bl, (s + 2) * 64, tid);

        const int buf = s % NPIPE;
        const float* Af = (const float*)(sm + buf * STAGE_B);
        const uint32_t bHb = sbase + buf * STAGE_B + A_PART_B + bRowOff;
        const uint32_t bLb = bHb + B_PART_B;

#pragma unroll
        for (int kk = 0; kk < 4; kk++) {
            const int col = kk * 16 + 2 * t;
            uint32_t ah[2][4], al[2][4];
#pragma unroll
            for (int mi = 0; mi < 2; mi++) {
                int r0 = wm * 32 + mi * 16 + g;
                float2 f0 = *(const float2*)&Af[(size_t)r0 * A_STRIDE_F + col];
                float2 f1 = *(const float2*)&Af[(size_t)(r0 + 8) * A_STRIDE_F + col];
                float2 f2 = *(const float2*)&Af[(size_t)r0 * A_STRIDE_F + col + 8];
                float2 f3 = *(const float2*)&Af[(size_t)(r0 + 8) * A_STRIDE_F + col + 8];
                split2(f0, ah[mi][0], al[mi][0]);
                split2(f1, ah[mi][1], al[mi][1]);
                split2(f2, ah[mi][2], al[mi][2]);
                split2(f3, ah[mi][3], al[mi][3]);
            }
            uint32_t bh[8][2], bl[8][2];
#pragma unroll
            for (int p = 0; p < 4; p++) {
                uint32_t r[4];
                ldsm_x4(r, bHb + p * (16 * B_ROW_B) + kk * 32);
                bh[2 * p][0] = r[0]; bh[2 * p + 1][0] = r[1];
                bh[2 * p][1] = r[2]; bh[2 * p + 1][1] = r[3];
                ldsm_x4(r, bLb + p * (16 * B_ROW_B) + kk * 32);
                bl[2 * p][0] = r[0]; bl[2 * p + 1][0] = r[1];
                bl[2 * p][1] = r[2]; bl[2 * p + 1][1] = r[3];
            }
#pragma unroll
            for (int mi = 0; mi < 2; mi++)
#pragma unroll
                for (int nj = 0; nj < 8; nj++)
                    mma_bf16(d[mi][nj], ah[mi], bh[nj][0], bh[nj][1]);
#pragma unroll
            for (int mi = 0; mi < 2; mi++)
#pragma unroll
                for (int nj = 0; nj < 8; nj++)
                    mma_bf16(d[mi][nj], ah[mi], bl[nj][0], bl[nj][1]);
#pragma unroll
            for (int mi = 0; mi < 2; mi++)
#pragma unroll
                for (int nj = 0; nj < 8; nj++)
                    mma_bf16(d[mi][nj], al[mi], bh[nj][0], bh[nj][1]);
        }
    }

#pragma unroll
    for (int nj = 0; nj < 8; nj++) {
        int cc = n0 + wn * 64 + nj * 8 + 2 * t;
        float2 bv = *(const float2*)&bias[cc];
#pragma unroll
        for (int mi = 0; mi < 2; mi++) {
            int r0 = m0 + wm * 32 + mi * 16 + g;
            float2 o0 = {d[mi][nj][0] + bv.x, d[mi][nj][1] + bv.y};
            float2 o1 = {d[mi][nj][2] + bv.x, d[mi][nj][3] + bv.y};
            __stcs((float2*)&C[(size_t)r0 * OUT_DIM + cc], o0);
            __stcs((float2*)&C[(size_t)(r0 + 8) * OUT_DIM + cc], o1);
        }
    }
}

// ================= Parallel scan, stage 1: chunk-local EMA sums ==============
// 8-deep load ring (MLP=8) to push DRAM toward the roofline.
__global__ __launch_bounds__(OUT_DIM)
void scan_s1_kernel(const float* __restrict__ decay, int T, int NCH) {
    const int bc = blockIdx.x;
    const int b  = bc / NCH;
    const int ch = bc % NCH;
    const int o  = threadIdx.x;
    if (ch == 0 && o == 0) g_flag[b] = 0;

    const float d = decay[o];
    const float omd = 1.f - d;
    const int t0 = ch * CH;
    const int len = min(T - t0, CH);
    const float* curB = g_cur + ((size_t)b * T + t0) * OUT_DIM + o;

    float c[8];
#pragma unroll
    for (int i = 0; i < 8; i++)
        c[i] = (i < len) ? __ldcs(curB + (size_t)i * OUT_DIM) : 0.f;

    float s = 0.f;
    int t = 0;
#pragma unroll 1
    for (; t + 8 <= len; t += 8) {
        float n[8];
#pragma unroll
        for (int u = 0; u < 8; u++)
            n[u] = (t + 8 + u < len) ? __ldcs(curB + (size_t)(t + 8 + u) * OUT_DIM) : 0.f;
#pragma unroll
        for (int u = 0; u < 8; u++)
            s = d * s + omd * c[u];
#pragma unroll
        for (int u = 0; u < 8; u++) c[u] = n[u];
    }
#pragma unroll 1
    for (int u = 0; t < len; t++, u++)
        s = d * s + omd * c[u];

    g_csum[(size_t)bc * OUT_DIM + o] = s;
}

// ================= stage 2: combine chunk boundaries ========================
__global__ __launch_bounds__(OUT_DIM)
void scan_s2_kernel(const float* __restrict__ decay, int T, int NCH) {
    const int b = blockIdx.x;
    const int o = threadIdx.x;
    const float d = decay[o];

    float dpCH = 1.f;
#pragma unroll 1
    for (int i = 0; i < CH; i++) dpCH *= d;

    float vb = 0.f;
#pragma unroll 1
    for (int ch = 0; ch < NCH; ch++) {
        g_vbound[((size_t)b * NCH + ch) * OUT_DIM + o] = vb;
        int len = min(CH, T - ch * CH);
        float dp = dpCH;
        if (len != CH) { dp = 1.f; for (int i = 0; i < len; i++) dp *= d; }
        vb = dp * vb + g_csum[((size_t)b * NCH + ch) * OUT_DIM + o];
    }
}

// ================= stage 3: expand no-spike trajectory + flag ================
// 6-deep read ring; streaming stores.
__global__ __launch_bounds__(OUT_DIM)
void scan_s3_kernel(const float* __restrict__ decay, int T, int NCH,
                    float* __restrict__ outputs,
                    float* __restrict__ statesV,
                    float* __restrict__ statesZ) {
    const int bc = blockIdx.x;
    const int b  = bc / NCH;
    const int ch = bc % NCH;
    const int o  = threadIdx.x;

    const float d = decay[o];
    const float omd = 1.f - d;
    const int t0 = ch * CH;
    const int len = min(T - t0, CH);

    const float* curB = g_cur + ((size_t)b * T + t0) * OUT_DIM + o;
    float* outB = outputs + ((size_t)b * T + t0) * OUT_DIM + o;
    float* svB  = statesV + ((size_t)b * (T + 1) + t0 + 1) * OUT_DIM + o;
    float* szB  = statesZ + ((size_t)b * (T + 1) + t0 + 1) * OUT_DIM + o;

    if (ch == 0) {
        statesV[((size_t)b * (T + 1)) * OUT_DIM + o] = 0.f;
        statesZ[((size_t)b * (T + 1)) * OUT_DIM + o] = 0.f;
    }

    float c[6];
#pragma unroll
    for (int i = 0; i < 6; i++)
        c[i] = (i < len) ? __ldcs(curB + (size_t)i * OUT_DIM) : 0.f;

    float v = g_vbound[(size_t)bc * OUT_DIM + o];
    bool spike = false;
    int t = 0;
#pragma unroll 1
    for (; t + 6 <= len; t += 6) {
        float n[6];
#pragma unroll
        for (int u = 0; u < 6; u++)
            n[u] = (t + 6 + u < len) ? __ldcs(curB + (size_t)(t + 6 + u) * OUT_DIM) : 0.f;
#pragma unroll
        for (int u = 0; u < 6; u++) {
            v = d * v + omd * c[u];
            float z = (v >= 1.f) ? 1.f : 0.f;
            spike |= (z > 0.f);
            size_t off = (size_t)(t + u) * OUT_DIM;
            __stcs(outB + off, z);
            __stcs(svB + off, v);
            __stcs(szB + off, z);
        }
#pragma unroll
        for (int u = 0; u < 6; u++) c[u] = n[u];
    }
#pragma unroll 1
    for (int u = 0; t < len; t++, u++) {
        v = d * v + omd * c[u];
        float z = (v >= 1.f) ? 1.f : 0.f;
        spike |= (z > 0.f);
        size_t off = (size_t)t * OUT_DIM;
        __stcs(outB + off, z);
        __stcs(svB + off, v);
        __stcs(szB + off, z);
    }
    if (__syncthreads_or(spike)) {
        if (o == 0) atomicOr(&g_flag[b], 1);
    }
}

// ================= stage 4: exact sequential fallback (flagged only) ========
__device__ __forceinline__ void lif_step(
    float c, float& v, float& z, int& anySpike,
    unsigned* smask, int o, int wid, int lane,
    float d, float omd,
    float* __restrict__ outB, float* __restrict__ svB, float* __restrict__ szB,
    int t)
{
    float soma = c;
    if (anySpike) {
#pragma unroll 1
        for (int w = 0; w < OUT_DIM / 32; w++) {
            unsigned m = smask[w];
            while (m) {
                int j = w * 32 + (__ffs(m) - 1);
                m &= (m - 1);
                soma += g_RT[(size_t)j * OUT_DIM + o];
            }
        }
    }
    v = d * (v * (1.f - z)) + omd * soma;
    z = (v >= 1.f) ? 1.f : 0.f;
    outB[(size_t)t * OUT_DIM + o]      = z;
    svB[(size_t)(t + 1) * OUT_DIM + o] = v;
    szB[(size_t)(t + 1) * OUT_DIM + o] = z;
    unsigned bal = __ballot_sync(0xffffffffu, z > 0.f);
    anySpike = __syncthreads_count(z > 0.f);
    if (anySpike) {
        if (lane == 0) smask[wid] = bal;
        __syncthreads();
    }
}

__global__ __launch_bounds__(OUT_DIM, 1)
void scan_s4_kernel(const float* __restrict__ decay,
                    float* __restrict__ outputs,
                    float* __restrict__ statesV,
                    float* __restrict__ statesZ,
                    int T) {
    const int b = blockIdx.x;
    if (g_flag[b] == 0) return;
    const int o = threadIdx.x;
    const int wid = o >> 5, lane = o & 31;

    __shared__ unsigned smask[OUT_DIM / 32];
    if (o < OUT_DIM / 32) smask[o] = 0u;

    const float d   = decay[o];
    const float omd = 1.f - d;

    const float* curB = g_cur + (size_t)b * T * OUT_DIM;
    float* outB = outputs + (size_t)b * T * OUT_DIM;
    float* svB  = statesV + (size_t)b * (T + 1) * OUT_DIM;
    float* szB  = statesZ + (size_t)b * (T + 1) * OUT_DIM;

    svB[o] = 0.f;
    szB[o] = 0.f;

    float v = 0.f, z = 0.f;
    int anySpike = 0;
    __syncthreads();

    float c0 = 0.f, c1 = 0.f, c2 = 0.f, c3 = 0.f;
    if (T > 0) c0 = curB[o];
    if (T > 1) c1 = curB[(size_t)OUT_DIM + o];
    if (T > 2) c2 = curB[(size_t)2 * OUT_DIM + o];
    if (T > 3) c3 = curB[(size_t)3 * OUT_DIM + o];

    int t = 0;
#pragma unroll 1
    for (; t + 3 < T; t += 4) {
        float n0 = (t + 4 < T) ? curB[(size_t)(t + 4) * OUT_DIM + o] : 0.f;
        lif_step(c0, v, z, anySpike, smask, o, wid, lane, d, omd, outB, svB, szB, t);
        float n1 = (t + 5 < T) ? curB[(size_t)(t + 5) * OUT_DIM + o] : 0.f;
        lif_step(c1, v, z, anySpike, smask, o, wid, lane, d, omd, outB, svB, szB, t + 1);
        float n2 = (t + 6 < T) ? curB[(size_t)(t + 6) * OUT_DIM + o] : 0.f;
        lif_step(c2, v, z, anySpike, smask, o, wid, lane, d, omd, outB, svB, szB, t + 2);
        float n3 = (t + 7 < T) ? curB[(size_t)(t + 7) * OUT_DIM + o] : 0.f;
        lif_step(c3, v, z, anySpike, smask, o, wid, lane, d, omd, outB, svB, szB, t + 3);
        c0 = n0; c1 = n1; c2 = n2; c3 = n3;
    }
    if (t < T) { lif_step(c0, v, z, anySpike, smask, o, wid, lane, d, omd, outB, svB, szB, t); t++; }
    if (t < T) { lif_step(c1, v, z, anySpike, smask, o, wid, lane, d, omd, outB, svB, szB, t); t++; }
    if (t < T) { lif_step(c2, v, z, anySpike, smask, o, wid, lane, d, omd, outB, svB, szB, t); t++; }
}

// ---------------------------------------------------------------------------
extern "C" void kernel_launch(void* const* d_in, const int* in_sizes, int n_in,
                              void* d_out, int out_size) {
    const float* x      = (const float*)d_in[0];  // [B, T, IN]
    const float* weight = (const float*)d_in[1];  // [OUT, IN]
    const float* bias   = (const float*)d_in[2];  // [OUT]
    const float* recur  = (const float*)d_in[3];  // [OUT, OUT]
    const float* decay  = (const float*)d_in[4];  // [OUT]

    const int OUT = in_sizes[2];                         // 512
    const int IN  = in_sizes[1] / OUT;                   // 512
    const long long M = (long long)in_sizes[0] / IN;     // B*T
    const long long B = (((long long)out_size / OUT) - 3 * M) / 2;
    const int T = (int)(M / B);
    const int NCH = (T + CH - 1) / CH;

    float* outputs = (float*)d_out;                        // [B,T,OUT]
    float* statesV = outputs + (size_t)B * T * OUT;        // [B,T+1,OUT]
    float* statesZ = statesV + (size_t)B * (T + 1) * OUT;  // [B,T+1,OUT]

    float* cur;
    cudaGetSymbolAddress((void**)&cur, g_cur);

    convert_w_kernel<<<(OUT * IN / 4) / 256, 256>>>(weight);
    {
        dim3 grid(OUT / 32, OUT / 32), block(32, 32);
        transpose512_kernel<<<grid, block>>>(recur);
    }

    cudaFuncSetAttribute(gemm_hmma_kernel,
                         cudaFuncAttributeMaxDynamicSharedMemorySize, SMEM_GEMM);
    {
        dim3 grid((unsigned)(M / 128), OUT / 128);
        gemm_hmma_kernel<<<grid, 256, SMEM_GEMM>>>(x, bias, cur);
    }

    scan_s1_kernel<<<(unsigned)(B * NCH), OUT>>>(decay, T, NCH);
    scan_s2_kernel<<<(unsigned)B, OUT>>>(decay, T, NCH);
    scan_s3_kernel<<<(unsigned)(B * NCH), OUT>>>(decay, T, NCH,
                                                 outputs, statesV, statesZ);
    scan_s4_kernel<<<(unsigned)B, OUT>>>(decay, outputs, statesV, statesZ, T);
}

// round 16
// speedup vs baseline: 1.2097x; 1.0043x over previous
#include <cuda_runtime.h>
#include <cuda_bf16.h>
#include <cstdint>

// ---------------------------------------------------------------------------
// LIF layer forward (sm_103 base ISA):
//   cur = x @ W^T + bias   (3-pass split-bf16 HMMA GEMM; A split fused in-kernel,
//                           B via ldmatrix.x4, 3-stage cp.async pipeline)
//   scan: v = d*v*(1-z) + (1-d)*(cur_t + z @ R^T);  z = (v >= 1)
// Scan chunk-parallelized (float4 path, 16 chunks) on the no-spike linear
// path + exact sequential fallback per batch element if any v >= THR.
// d_out = [outputs | statesV | statesZ]
// ---------------------------------------------------------------------------

#define IN_DIM  512
#define OUT_DIM 512
#define MAX_M   64000
#define MAX_B   128
#define CH      63
#define MAX_NCH 16

__device__ __nv_bfloat16 g_whi[(size_t)OUT_DIM * IN_DIM];
__device__ __nv_bfloat16 g_wlo[(size_t)OUT_DIM * IN_DIM];
__device__ float         g_RT [(size_t)OUT_DIM * OUT_DIM];
__device__ float         g_cur[(size_t)MAX_M * OUT_DIM];
__device__ float         g_csum  [(size_t)MAX_B * MAX_NCH * OUT_DIM];
__device__ float         g_vbound[(size_t)MAX_B * MAX_NCH * OUT_DIM];
__device__ int           g_flag[MAX_B];

// ======================= small prep kernels =================================
__global__ void convert_w_kernel(const float* __restrict__ w) {
    int i = blockIdx.x * blockDim.x + threadIdx.x;
    float4 v = ((const float4*)w)[i];
    float vv[4] = {v.x, v.y, v.z, v.w};
    __nv_bfloat16 h[4], l[4];
#pragma unroll
    for (int k = 0; k < 4; k++) {
        h[k] = __float2bfloat16_rn(vv[k]);
        l[k] = __float2bfloat16_rn(vv[k] - __bfloat162float(h[k]));
    }
    __nv_bfloat162* hi2 = (__nv_bfloat162*)g_whi;
    __nv_bfloat162* lo2 = (__nv_bfloat162*)g_wlo;
    hi2[i * 2]     = __halves2bfloat162(h[0], h[1]);
    hi2[i * 2 + 1] = __halves2bfloat162(h[2], h[3]);
    lo2[i * 2]     = __halves2bfloat162(l[0], l[1]);
    lo2[i * 2 + 1] = __halves2bfloat162(l[2], l[3]);
}

__global__ void transpose512_kernel(const float* __restrict__ R) {
    __shared__ float tile[32][33];
    int x = blockIdx.x * 32 + threadIdx.x;
    int y = blockIdx.y * 32 + threadIdx.y;
    tile[threadIdx.y][threadIdx.x] = R[y * OUT_DIM + x];
    __syncthreads();
    int xo = blockIdx.y * 32 + threadIdx.x;
    int yo = blockIdx.x * 32 + threadIdx.y;
    g_RT[yo * OUT_DIM + xo] = tile[threadIdx.x][threadIdx.y];
}

// ======================= HMMA GEMM (R12-proven config) ======================
#define A_STRIDE_F 68
#define A_PART_B   (128 * A_STRIDE_F * 4)       // 34816
#define B_STRIDE   72
#define B_ROW_B    (B_STRIDE * 2)               // 144
#define B_PART_B   (128 * B_ROW_B)              // 18432
#define STAGE_B    (A_PART_B + 2 * B_PART_B)    // 71680
#define NPIPE      3
#define SMEM_GEMM  (NPIPE * STAGE_B)            // 215040

__device__ __forceinline__ uint32_t smem_u32(const void* p) {
    uint32_t a;
    asm("{ .reg .u64 t; cvta.to.shared.u64 t, %1; cvt.u32.u64 %0, t; }"
        : "=r"(a) : "l"(p));
    return a;
}

__device__ __forceinline__ void cp16(void* dst, const void* src) {
    uint32_t d;
    asm("{ .reg .u64 t; cvta.to.shared.u64 t, %1; cvt.u32.u64 %0, t; }"
        : "=r"(d) : "l"(dst));
    asm volatile("cp.async.cg.shared.global [%0], [%1], 16;" :: "r"(d), "l"(src));
}

__device__ __forceinline__ void ldsm_x4(uint32_t* r, uint32_t addr) {
    asm volatile("ldmatrix.sync.aligned.m8n8.x4.shared.b16 {%0,%1,%2,%3}, [%4];"
        : "=r"(r[0]), "=r"(r[1]), "=r"(r[2]), "=r"(r[3]) : "r"(addr));
}

__device__ __forceinline__ void mma_bf16(float* d, const uint32_t* a,
                                         uint32_t b0, uint32_t b1) {
    asm volatile(
        "mma.sync.aligned.m16n8k16.row.col.f32.bf16.bf16.f32 "
        "{%0,%1,%2,%3}, {%4,%5,%6,%7}, {%8,%9}, {%0,%1,%2,%3};"
        : "+f"(d[0]), "+f"(d[1]), "+f"(d[2]), "+f"(d[3])
        : "r"(a[0]), "r"(a[1]), "r"(a[2]), "r"(a[3]), "r"(b0), "r"(b1));
}

__device__ __forceinline__ void split2(float2 f, uint32_t& h, uint32_t& l) {
    asm("cvt.rn.bf16x2.f32 %0, %1, %2;" : "=r"(h) : "f"(f.y), "f"(f.x));
    float h0 = __uint_as_float(h << 16);
    float h1 = __uint_as_float(h & 0xffff0000u);
    float l0 = f.x - h0;
    float l1 = f.y - h1;
    asm("cvt.rn.bf16x2.f32 %0, %1, %2;" : "=r"(l) : "f"(l1), "f"(l0));
}

__device__ __forceinline__ void load_stage(char* sm, int buf,
        const float* A, const __nv_bfloat16* Bh, const __nv_bfloat16* Bl,
        int k0, int tid) {
    char* base = sm + buf * STAGE_B;
    {
        const float* gp = A + k0;
#pragma unroll
        for (int it = 0; it < 8; it++) {
            int chunk = it * 256 + tid;
            int row = chunk >> 4;
            int cc  = chunk & 15;
            cp16(base + row * (A_STRIDE_F * 4) + cc * 16,
                 gp + (size_t)row * IN_DIM + cc * 4);
        }
    }
    const __nv_bfloat16* srcs[2] = {Bh, Bl};
#pragma unroll
    for (int p = 0; p < 2; p++) {
        char* pb = base + A_PART_B + p * B_PART_B;
        const __nv_bfloat16* gp = srcs[p] + k0;
#pragma unroll
        for (int it = 0; it < 4; it++) {
            int chunk = it * 256 + tid;
            int row = chunk >> 3;
            int cc  = chunk & 7;
            cp16(pb + row * B_ROW_B + cc * 16,
                 gp + (size_t)row * IN_DIM + cc * 8);
        }
    }
    asm volatile("cp.async.commit_group;");
}

__global__ __launch_bounds__(256)
void gemm_hmma_kernel(const float* __restrict__ x,
                      const float* __restrict__ bias,
                      float* __restrict__ C) {
    extern __shared__ char sm[];
    const uint32_t sbase = smem_u32(sm);
    const int tid  = threadIdx.x;
    const int wid  = tid >> 5;
    const int lane = tid & 31;
    const int g = lane >> 2, t = lane & 3;
    const int wm = wid >> 1;
    const int wn = wid & 1;
    const int m0 = blockIdx.x * 128;
    const int n0 = blockIdx.y * 128;

    const float*         A  = x     + (size_t)m0 * IN_DIM;
    const __nv_bfloat16* Bh = g_whi + (size_t)n0 * IN_DIM;
    const __nv_bfloat16* Bl = g_wlo + (size_t)n0 * IN_DIM;

    const uint32_t bRowOff = (uint32_t)(wn * 64 + (lane & 15)) * B_ROW_B
                           + (uint32_t)(lane >> 4) * 16;

    float d[2][8][4];
#pragma unroll
    for (int mi = 0; mi < 2; mi++)
#pragma unroll
        for (int nj = 0; nj < 8; nj++)
#pragma unroll
            for (int r = 0; r < 4; r++) d[mi][nj][r] = 0.f;

    load_stage(sm, 0, A, Bh, Bl, 0, tid);
    load_stage(sm, 1, A, Bh, Bl, 64, tid);

#pragma unroll 1
    for (int s = 0; s < 8; s++) {
        if (s < 7) {
            asm volatile("cp.async.wait_group 1;");
        } else {
            asm volatile("cp.async.wait_group 0;");
        }
        __syncthreads();

        if (s + 2 < 8)
            load_stage(sm, (s + 2) % NPIPE, A, Bh, Bl, (s + 2) * 64, tid);

        const int buf = s % NPIPE;
        const float* Af = (const float*)(sm + buf * STAGE_B);
        const uint32_t bHb = sbase + buf * STAGE_B + A_PART_B + bRowOff;
        const uint32_t bLb = bHb + B_PART_B;

#pragma unroll
        for (int kk = 0; kk < 4; kk++) {
            const int col = kk * 16 + 2 * t;
            uint32_t ah[2][4], al[2][4];
#pragma unroll
            for (int mi = 0; mi < 2; mi++) {
                int r0 = wm * 32 + mi * 16 + g;
                float2 f0 = *(const float2*)&Af[(size_t)r0 * A_STRIDE_F + col];
                float2 f1 = *(const float2*)&Af[(size_t)(r0 + 8) * A_STRIDE_F + col];
                float2 f2 = *(const float2*)&Af[(size_t)r0 * A_STRIDE_F + col + 8];
                float2 f3 = *(const float2*)&Af[(size_t)(r0 + 8) * A_STRIDE_F + col + 8];
                split2(f0, ah[mi][0], al[mi][0]);
                split2(f1, ah[mi][1], al[mi][1]);
                split2(f2, ah[mi][2], al[mi][2]);
                split2(f3, ah[mi][3], al[mi][3]);
            }
            uint32_t bh[8][2], bl[8][2];
#pragma unroll
            for (int p = 0; p < 4; p++) {
                uint32_t r[4];
                ldsm_x4(r, bHb + p * (16 * B_ROW_B) + kk * 32);
                bh[2 * p][0] = r[0]; bh[2 * p + 1][0] = r[1];
                bh[2 * p][1] = r[2]; bh[2 * p + 1][1] = r[3];
                ldsm_x4(r, bLb + p * (16 * B_ROW_B) + kk * 32);
                bl[2 * p][0] = r[0]; bl[2 * p + 1][0] = r[1];
                bl[2 * p][1] = r[2]; bl[2 * p + 1][1] = r[3];
            }
#pragma unroll
            for (int mi = 0; mi < 2; mi++)
#pragma unroll
                for (int nj = 0; nj < 8; nj++)
                    mma_bf16(d[mi][nj], ah[mi], bh[nj][0], bh[nj][1]);
#pragma unroll
            for (int mi = 0; mi < 2; mi++)
#pragma unroll
                for (int nj = 0; nj < 8; nj++)
                    mma_bf16(d[mi][nj], ah[mi], bl[nj][0], bl[nj][1]);
#pragma unroll
            for (int mi = 0; mi < 2; mi++)
#pragma unroll
                for (int nj = 0; nj < 8; nj++)
                    mma_bf16(d[mi][nj], al[mi], bh[nj][0], bh[nj][1]);
        }
    }

#pragma unroll
    for (int nj = 0; nj < 8; nj++) {
        int cc = n0 + wn * 64 + nj * 8 + 2 * t;
        float2 bv = *(const float2*)&bias[cc];
#pragma unroll
        for (int mi = 0; mi < 2; mi++) {
            int r0 = m0 + wm * 32 + mi * 16 + g;
            float2 o0 = {d[mi][nj][0] + bv.x, d[mi][nj][1] + bv.y};
            float2 o1 = {d[mi][nj][2] + bv.x, d[mi][nj][3] + bv.y};
            __stcs((float2*)&C[(size_t)r0 * OUT_DIM + cc], o0);
            __stcs((float2*)&C[(size_t)(r0 + 8) * OUT_DIM + cc], o1);
        }
    }
}

// ================= Parallel scan, stage 1: chunk-local EMA sums ==============
// 128 threads x 4 neurons (float4); 4-deep float4 ring (64B in flight/thread).
__global__ __launch_bounds__(128)
void scan_s1_kernel(const float* __restrict__ decay, int T, int NCH) {
    const int bc = blockIdx.x;
    const int b  = bc / NCH;
    const int ch = bc % NCH;
    const int o4 = threadIdx.x * 4;
    if (ch == 0 && threadIdx.x == 0) g_flag[b] = 0;

    const float4 dd = *(const float4*)&decay[o4];
    const float4 om = {1.f - dd.x, 1.f - dd.y, 1.f - dd.z, 1.f - dd.w};
    const int t0 = ch * CH;
    const int len = min(T - t0, CH);
    const float* curB = g_cur + ((size_t)b * T + t0) * OUT_DIM + o4;

    const float4 zero4 = {0.f, 0.f, 0.f, 0.f};
    float4 c[4];
#pragma unroll
    for (int i = 0; i < 4; i++)
        c[i] = (i < len) ? __ldcs((const float4*)(curB + (size_t)i * OUT_DIM)) : zero4;

    float4 s = zero4;
    int t = 0;
#pragma unroll 1
    for (; t + 4 <= len; t += 4) {
        float4 n[4];
#pragma unroll
        for (int u = 0; u < 4; u++)
            n[u] = (t + 4 + u < len)
                 ? __ldcs((const float4*)(curB + (size_t)(t + 4 + u) * OUT_DIM)) : zero4;
#pragma unroll
        for (int u = 0; u < 4; u++) {
            s.x = dd.x * s.x + om.x * c[u].x;
            s.y = dd.y * s.y + om.y * c[u].y;
            s.z = dd.z * s.z + om.z * c[u].z;
            s.w = dd.w * s.w + om.w * c[u].w;
        }
#pragma unroll
        for (int u = 0; u < 4; u++) c[u] = n[u];
    }
#pragma unroll 1
    for (int u = 0; t < len; t++, u++) {
        s.x = dd.x * s.x + om.x * c[u].x;
        s.y = dd.y * s.y + om.y * c[u].y;
        s.z = dd.z * s.z + om.z * c[u].z;
        s.w = dd.w * s.w + om.w * c[u].w;
    }

    *(float4*)&g_csum[(size_t)bc * OUT_DIM + o4] = s;
}

// ================= stage 2: combine chunk boundaries ========================
__global__ __launch_bounds__(OUT_DIM)
void scan_s2_kernel(const float* __restrict__ decay, int T, int NCH) {
    const int b = blockIdx.x;
    const int o = threadIdx.x;
    const float d = decay[o];

    float dpCH = 1.f;
#pragma unroll 1
    for (int i = 0; i < CH; i++) dpCH *= d;

    float vb = 0.f;
#pragma unroll 1
    for (int ch = 0; ch < NCH; ch++) {
        g_vbound[((size_t)b * NCH + ch) * OUT_DIM + o] = vb;
        int len = min(CH, T - ch * CH);
        float dp = dpCH;
        if (len != CH) { dp = 1.f; for (int i = 0; i < len; i++) dp *= d; }
        vb = dp * vb + g_csum[((size_t)b * NCH + ch) * OUT_DIM + o];
    }
}

// ================= stage 3: expand no-spike trajectory + flag ================
// 128 threads x 4 neurons; float4 loads/stores; 4-deep read ring.
__global__ __launch_bounds__(128)
void scan_s3_kernel(const float* __restrict__ decay, int T, int NCH,
                    float* __restrict__ outputs,
                    float* __restrict__ statesV,
                    float* __restrict__ statesZ) {
    const int bc = blockIdx.x;
    const int b  = bc / NCH;
    const int ch = bc % NCH;
    const int o4 = threadIdx.x * 4;

    const float4 dd = *(const float4*)&decay[o4];
    const float4 om = {1.f - dd.x, 1.f - dd.y, 1.f - dd.z, 1.f - dd.w};
    const int t0 = ch * CH;
    const int len = min(T - t0, CH);

    const float* curB = g_cur + ((size_t)b * T + t0) * OUT_DIM + o4;
    float* outB = outputs + ((size_t)b * T + t0) * OUT_DIM + o4;
    float* svB  = statesV + ((size_t)b * (T + 1) + t0 + 1) * OUT_DIM + o4;
    float* szB  = statesZ + ((size_t)b * (T + 1) + t0 + 1) * OUT_DIM + o4;

    const float4 zero4 = {0.f, 0.f, 0.f, 0.f};
    if (ch == 0) {
        *(float4*)&statesV[((size_t)b * (T + 1)) * OUT_DIM + o4] = zero4;
        *(float4*)&statesZ[((size_t)b * (T + 1)) * OUT_DIM + o4] = zero4;
    }

    float4 c[4];
#pragma unroll
    for (int i = 0; i < 4; i++)
        c[i] = (i < len) ? __ldcs((const float4*)(curB + (size_t)i * OUT_DIM)) : zero4;

    float4 v = *(const float4*)&g_vbound[(size_t)bc * OUT_DIM + o4];
    bool spike = false;
    int t = 0;
#pragma unroll 1
    for (; t + 4 <= len; t += 4) {
        float4 n[4];
#pragma unroll
        for (int u = 0; u < 4; u++)
            n[u] = (t + 4 + u < len)
                 ? __ldcs((const float4*)(curB + (size_t)(t + 4 + u) * OUT_DIM)) : zero4;
#pragma unroll
        for (int u = 0; u < 4; u++) {
            v.x = dd.x * v.x + om.x * c[u].x;
            v.y = dd.y * v.y + om.y * c[u].y;
            v.z = dd.z * v.z + om.z * c[u].z;
            v.w = dd.w * v.w + om.w * c[u].w;
            float4 z = {(v.x >= 1.f) ? 1.f : 0.f, (v.y >= 1.f) ? 1.f : 0.f,
                        (v.z >= 1.f) ? 1.f : 0.f, (v.w >= 1.f) ? 1.f : 0.f};
            spike |= (z.x + z.y + z.z + z.w) > 0.f;
            size_t off = (size_t)(t + u) * OUT_DIM;
            __stcs((float4*)(outB + off), z);
            __stcs((float4*)(svB + off), v);
            __stcs((float4*)(szB + off), z);
        }
#pragma unroll
        for (int u = 0; u < 4; u++) c[u] = n[u];
    }
#pragma unroll 1
    for (int u = 0; t < len; t++, u++) {
        v.x = dd.x * v.x + om.x * c[u].x;
        v.y = dd.y * v.y + om.y * c[u].y;
        v.z = dd.z * v.z + om.z * c[u].z;
        v.w = dd.w * v.w + om.w * c[u].w;
        float4 z = {(v.x >= 1.f) ? 1.f : 0.f, (v.y >= 1.f) ? 1.f : 0.f,
                    (v.z >= 1.f) ? 1.f : 0.f, (v.w >= 1.f) ? 1.f : 0.f};
        spike |= (z.x + z.y + z.z + z.w) > 0.f;
        size_t off = (size_t)t * OUT_DIM;
        __stcs((float4*)(outB + off), z);
        __stcs((float4*)(svB + off), v);
        __stcs((float4*)(szB + off), z);
    }
    if (__syncthreads_or(spike)) {
        if (threadIdx.x == 0) atomicOr(&g_flag[b], 1);
    }
}

// ================= stage 4: exact sequential fallback (flagged only) ========
__device__ __forceinline__ void lif_step(
    float c, float& v, float& z, int& anySpike,
    unsigned* smask, int o, int wid, int lane,
    float d, float omd,
    float* __restrict__ outB, float* __restrict__ svB, float* __restrict__ szB,
    int t)
{
    float soma = c;
    if (anySpike) {
#pragma unroll 1
        for (int w = 0; w < OUT_DIM / 32; w++) {
            unsigned m = smask[w];
            while (m) {
                int j = w * 32 + (__ffs(m) - 1);
                m &= (m - 1);
                soma += g_RT[(size_t)j * OUT_DIM + o];
            }
        }
    }
    v = d * (v * (1.f - z)) + omd * soma;
    z = (v >= 1.f) ? 1.f : 0.f;
    outB[(size_t)t * OUT_DIM + o]      = z;
    svB[(size_t)(t + 1) * OUT_DIM + o] = v;
    szB[(size_t)(t + 1) * OUT_DIM + o] = z;
    unsigned bal = __ballot_sync(0xffffffffu, z > 0.f);
    anySpike = __syncthreads_count(z > 0.f);
    if (anySpike) {
        if (lane == 0) smask[wid] = bal;
        __syncthreads();
    }
}

__global__ __launch_bounds__(OUT_DIM, 1)
void scan_s4_kernel(const float* __restrict__ decay,
                    float* __restrict__ outputs,
                    float* __restrict__ statesV,
                    float* __restrict__ statesZ,
                    int T) {
    const int b = blockIdx.x;
    if (g_flag[b] == 0) return;
    const int o = threadIdx.x;
    const int wid = o >> 5, lane = o & 31;

    __shared__ unsigned smask[OUT_DIM / 32];
    if (o < OUT_DIM / 32) smask[o] = 0u;

    const float d   = decay[o];
    const float omd = 1.f - d;

    const float* curB = g_cur + (size_t)b * T * OUT_DIM;
    float* outB = outputs + (size_t)b * T * OUT_DIM;
    float* svB  = statesV + (size_t)b * (T + 1) * OUT_DIM;
    float* szB  = statesZ + (size_t)b * (T + 1) * OUT_DIM;

    svB[o] = 0.f;
    szB[o] = 0.f;

    float v = 0.f, z = 0.f;
    int anySpike = 0;
    __syncthreads();

    float c0 = 0.f, c1 = 0.f, c2 = 0.f, c3 = 0.f;
    if (T > 0) c0 = curB[o];
    if (T > 1) c1 = curB[(size_t)OUT_DIM + o];
    if (T > 2) c2 = curB[(size_t)2 * OUT_DIM + o];
    if (T > 3) c3 = curB[(size_t)3 * OUT_DIM + o];

    int t = 0;
#pragma unroll 1
    for (; t + 3 < T; t += 4) {
        float n0 = (t + 4 < T) ? curB[(size_t)(t + 4) * OUT_DIM + o] : 0.f;
        lif_step(c0, v, z, anySpike, smask, o, wid, lane, d, omd, outB, svB, szB, t);
        float n1 = (t + 5 < T) ? curB[(size_t)(t + 5) * OUT_DIM + o] : 0.f;
        lif_step(c1, v, z, anySpike, smask, o, wid, lane, d, omd, outB, svB, szB, t + 1);
        float n2 = (t + 6 < T) ? curB[(size_t)(t + 6) * OUT_DIM + o] : 0.f;
        lif_step(c2, v, z, anySpike, smask, o, wid, lane, d, omd, outB, svB, szB, t + 2);
        float n3 = (t + 7 < T) ? curB[(size_t)(t + 7) * OUT_DIM + o] : 0.f;
        lif_step(c3, v, z, anySpike, smask, o, wid, lane, d, omd, outB, svB, szB, t + 3);
        c0 = n0; c1 = n1; c2 = n2; c3 = n3;
    }
    if (t < T) { lif_step(c0, v, z, anySpike, smask, o, wid, lane, d, omd, outB, svB, szB, t); t++; }
    if (t < T) { lif_step(c1, v, z, anySpike, smask, o, wid, lane, d, omd, outB, svB, szB, t); t++; }
    if (t < T) { lif_step(c2, v, z, anySpike, smask, o, wid, lane, d, omd, outB, svB, szB, t); t++; }
}

// ---------------------------------------------------------------------------
extern "C" void kernel_launch(void* const* d_in, const int* in_sizes, int n_in,
                              void* d_out, int out_size) {
    const float* x      = (const float*)d_in[0];  // [B, T, IN]
    const float* weight = (const float*)d_in[1];  // [OUT, IN]
    const float* bias   = (const float*)d_in[2];  // [OUT]
    const float* recur  = (const float*)d_in[3];  // [OUT, OUT]
    const float* decay  = (const float*)d_in[4];  // [OUT]

    const int OUT = in_sizes[2];                         // 512
    const int IN  = in_sizes[1] / OUT;                   // 512
    const long long M = (long long)in_sizes[0] / IN;     // B*T
    const long long B = (((long long)out_size / OUT) - 3 * M) / 2;
    const int T = (int)(M / B);
    const int NCH = (T + CH - 1) / CH;                   // 16 for T=1000

    float* outputs = (float*)d_out;                        // [B,T,OUT]
    float* statesV = outputs + (size_t)B * T * OUT;        // [B,T+1,OUT]
    float* statesZ = statesV + (size_t)B * (T + 1) * OUT;  // [B,T+1,OUT]

    float* cur;
    cudaGetSymbolAddress((void**)&cur, g_cur);

    convert_w_kernel<<<(OUT * IN / 4) / 256, 256>>>(weight);
    {
        dim3 grid(OUT / 32, OUT / 32), block(32, 32);
        transpose512_kernel<<<grid, block>>>(recur);
    }

    cudaFuncSetAttribute(gemm_hmma_kernel,
                         cudaFuncAttributeMaxDynamicSharedMemorySize, SMEM_GEMM);
    {
        dim3 grid((unsigned)(M / 128), OUT / 128);
        gemm_hmma_kernel<<<grid, 256, SMEM_GEMM>>>(x, bias, cur);
    }

    scan_s1_kernel<<<(unsigned)(B * NCH), 128>>>(decay, T, NCH);
    scan_s2_kernel<<<(unsigned)B, OUT>>>(decay, T, NCH);
    scan_s3_kernel<<<(unsigned)(B * NCH), 128>>>(decay, T, NCH,
                                                 outputs, statesV, statesZ);
    scan_s4_kernel<<<(unsigned)B, OUT>>>(decay, outputs, statesV, statesZ, T);
}

// round 17
// speedup vs baseline: 1.2168x; 1.0058x over previous
#include <cuda_runtime.h>
#include <cuda_bf16.h>
#include <cstdint>

// ---------------------------------------------------------------------------
// LIF layer forward (sm_103 base ISA):
//   cur = x @ W^T + bias   (3-pass split-bf16 HMMA GEMM; A split fused in-kernel,
//                           B via ldmatrix.x4, 3-stage cp.async pipeline)
//   scan: v = d*v*(1-z) + (1-d)*(cur_t + z @ R^T);  z = (v >= 1)
// Scan chunk-parallelized (float4, 16 chunks; boundary combine fused into the
// expand stage) on the no-spike linear path + exact sequential fallback per
// batch element if any v >= THR. cur kept L2-warm between GEMM and scans.
// d_out = [outputs | statesV | statesZ]
// ---------------------------------------------------------------------------

#define IN_DIM  512
#define OUT_DIM 512
#define MAX_M   64000
#define MAX_B   128
#define CH      63
#define MAX_NCH 16

__device__ __nv_bfloat16 g_whi[(size_t)OUT_DIM * IN_DIM];
__device__ __nv_bfloat16 g_wlo[(size_t)OUT_DIM * IN_DIM];
__device__ float         g_RT [(size_t)OUT_DIM * OUT_DIM];
__device__ float         g_cur[(size_t)MAX_M * OUT_DIM];
__device__ float         g_csum[(size_t)MAX_B * MAX_NCH * OUT_DIM];
__device__ int           g_flag[MAX_B];

// ======================= small prep kernels =================================
__global__ void convert_w_kernel(const float* __restrict__ w) {
    int i = blockIdx.x * blockDim.x + threadIdx.x;
    float4 v = ((const float4*)w)[i];
    float vv[4] = {v.x, v.y, v.z, v.w};
    __nv_bfloat16 h[4], l[4];
#pragma unroll
    for (int k = 0; k < 4; k++) {
        h[k] = __float2bfloat16_rn(vv[k]);
        l[k] = __float2bfloat16_rn(vv[k] - __bfloat162float(h[k]));
    }
    __nv_bfloat162* hi2 = (__nv_bfloat162*)g_whi;
    __nv_bfloat162* lo2 = (__nv_bfloat162*)g_wlo;
    hi2[i * 2]     = __halves2bfloat162(h[0], h[1]);
    hi2[i * 2 + 1] = __halves2bfloat162(h[2], h[3]);
    lo2[i * 2]     = __halves2bfloat162(l[0], l[1]);
    lo2[i * 2 + 1] = __halves2bfloat162(l[2], l[3]);
}

__global__ void transpose512_kernel(const float* __restrict__ R) {
    __shared__ float tile[32][33];
    int x = blockIdx.x * 32 + threadIdx.x;
    int y = blockIdx.y * 32 + threadIdx.y;
    tile[threadIdx.y][threadIdx.x] = R[y * OUT_DIM + x];
    __syncthreads();
    int xo = blockIdx.y * 32 + threadIdx.x;
    int yo = blockIdx.x * 32 + threadIdx.y;
    g_RT[yo * OUT_DIM + xo] = tile[threadIdx.x][threadIdx.y];
}

// ======================= HMMA GEMM (R12-proven config) ======================
#define A_STRIDE_F 68
#define A_PART_B   (128 * A_STRIDE_F * 4)       // 34816
#define B_STRIDE   72
#define B_ROW_B    (B_STRIDE * 2)               // 144
#define B_PART_B   (128 * B_ROW_B)              // 18432
#define STAGE_B    (A_PART_B + 2 * B_PART_B)    // 71680
#define NPIPE      3
#define SMEM_GEMM  (NPIPE * STAGE_B)            // 215040

__device__ __forceinline__ uint32_t smem_u32(const void* p) {
    uint32_t a;
    asm("{ .reg .u64 t; cvta.to.shared.u64 t, %1; cvt.u32.u64 %0, t; }"
        : "=r"(a) : "l"(p));
    return a;
}

__device__ __forceinline__ void cp16(void* dst, const void* src) {
    uint32_t d;
    asm("{ .reg .u64 t; cvta.to.shared.u64 t, %1; cvt.u32.u64 %0, t; }"
        : "=r"(d) : "l"(dst));
    asm volatile("cp.async.cg.shared.global [%0], [%1], 16;" :: "r"(d), "l"(src));
}

__device__ __forceinline__ void ldsm_x4(uint32_t* r, uint32_t addr) {
    asm volatile("ldmatrix.sync.aligned.m8n8.x4.shared.b16 {%0,%1,%2,%3}, [%4];"
        : "=r"(r[0]), "=r"(r[1]), "=r"(r[2]), "=r"(r[3]) : "r"(addr));
}

__device__ __forceinline__ void mma_bf16(float* d, const uint32_t* a,
                                         uint32_t b0, uint32_t b1) {
    asm volatile(
        "mma.sync.aligned.m16n8k16.row.col.f32.bf16.bf16.f32 "
        "{%0,%1,%2,%3}, {%4,%5,%6,%7}, {%8,%9}, {%0,%1,%2,%3};"
        : "+f"(d[0]), "+f"(d[1]), "+f"(d[2]), "+f"(d[3])
        : "r"(a[0]), "r"(a[1]), "r"(a[2]), "r"(a[3]), "r"(b0), "r"(b1));
}

__device__ __forceinline__ void split2(float2 f, uint32_t& h, uint32_t& l) {
    asm("cvt.rn.bf16x2.f32 %0, %1, %2;" : "=r"(h) : "f"(f.y), "f"(f.x));
    float h0 = __uint_as_float(h << 16);
    float h1 = __uint_as_float(h & 0xffff0000u);
    float l0 = f.x - h0;
    float l1 = f.y - h1;
    asm("cvt.rn.bf16x2.f32 %0, %1, %2;" : "=r"(l) : "f"(l1), "f"(l0));
}

__device__ __forceinline__ void load_stage(char* sm, int buf,
        const float* A, const __nv_bfloat16* Bh, const __nv_bfloat16* Bl,
        int k0, int tid) {
    char* base = sm + buf * STAGE_B;
    {
        const float* gp = A + k0;
#pragma unroll
        for (int it = 0; it < 8; it++) {
            int chunk = it * 256 + tid;
            int row = chunk >> 4;
            int cc  = chunk & 15;
            cp16(base + row * (A_STRIDE_F * 4) + cc * 16,
                 gp + (size_t)row * IN_DIM + cc * 4);
        }
    }
    const __nv_bfloat16* srcs[2] = {Bh, Bl};
#pragma unroll
    for (int p = 0; p < 2; p++) {
        char* pb = base + A_PART_B + p * B_PART_B;
        const __nv_bfloat16* gp = srcs[p] + k0;
#pragma unroll
        for (int it = 0; it < 4; it++) {
            int chunk = it * 256 + tid;
            int row = chunk >> 3;
            int cc  = chunk & 7;
            cp16(pb + row * B_ROW_B + cc * 16,
                 gp + (size_t)row * IN_DIM + cc * 8);
        }
    }
    asm volatile("cp.async.commit_group;");
}

__global__ __launch_bounds__(256)
void gemm_hmma_kernel(const float* __restrict__ x,
                      const float* __restrict__ bias,
                      float* __restrict__ C) {
    extern __shared__ char sm[];
    const uint32_t sbase = smem_u32(sm);
    const int tid  = threadIdx.x;
    const int wid  = tid >> 5;
    const int lane = tid & 31;
    const int g = lane >> 2, t = lane & 3;
    const int wm = wid >> 1;
    const int wn = wid & 1;
    const int m0 = blockIdx.x * 128;
    const int n0 = blockIdx.y * 128;

    const float*         A  = x     + (size_t)m0 * IN_DIM;
    const __nv_bfloat16* Bh = g_whi + (size_t)n0 * IN_DIM;
    const __nv_bfloat16* Bl = g_wlo + (size_t)n0 * IN_DIM;

    const uint32_t bRowOff = (uint32_t)(wn * 64 + (lane & 15)) * B_ROW_B
                           + (uint32_t)(lane >> 4) * 16;

    float d[2][8][4];
#pragma unroll
    for (int mi = 0; mi < 2; mi++)
#pragma unroll
        for (int nj = 0; nj < 8; nj++)
#pragma unroll
            for (int r = 0; r < 4; r++) d[mi][nj][r] = 0.f;

    load_stage(sm, 0, A, Bh, Bl, 0, tid);
    load_stage(sm, 1, A, Bh, Bl, 64, tid);

#pragma unroll 1
    for (int s = 0; s < 8; s++) {
        if (s < 7) {
            asm volatile("cp.async.wait_group 1;");
        } else {
            asm volatile("cp.async.wait_group 0;");
        }
        __syncthreads();

        if (s + 2 < 8)
            load_stage(sm, (s + 2) % NPIPE, A, Bh, Bl, (s + 2) * 64, tid);

        const int buf = s % NPIPE;
        const float* Af = (const float*)(sm + buf * STAGE_B);
        const uint32_t bHb = sbase + buf * STAGE_B + A_PART_B + bRowOff;
        const uint32_t bLb = bHb + B_PART_B;

#pragma unroll
        for (int kk = 0; kk < 4; kk++) {
            const int col = kk * 16 + 2 * t;
            uint32_t ah[2][4], al[2][4];
#pragma unroll
            for (int mi = 0; mi < 2; mi++) {
                int r0 = wm * 32 + mi * 16 + g;
                float2 f0 = *(const float2*)&Af[(size_t)r0 * A_STRIDE_F + col];
                float2 f1 = *(const float2*)&Af[(size_t)(r0 + 8) * A_STRIDE_F + col];
                float2 f2 = *(const float2*)&Af[(size_t)r0 * A_STRIDE_F + col + 8];
                float2 f3 = *(const float2*)&Af[(size_t)(r0 + 8) * A_STRIDE_F + col + 8];
                split2(f0, ah[mi][0], al[mi][0]);
                split2(f1, ah[mi][1], al[mi][1]);
                split2(f2, ah[mi][2], al[mi][2]);
                split2(f3, ah[mi][3], al[mi][3]);
            }
            uint32_t bh[8][2], bl[8][2];
#pragma unroll
            for (int p = 0; p < 4; p++) {
                uint32_t r[4];
                ldsm_x4(r, bHb + p * (16 * B_ROW_B) + kk * 32);
                bh[2 * p][0] = r[0]; bh[2 * p + 1][0] = r[1];
                bh[2 * p][1] = r[2]; bh[2 * p + 1][1] = r[3];
                ldsm_x4(r, bLb + p * (16 * B_ROW_B) + kk * 32);
                bl[2 * p][0] = r[0]; bl[2 * p + 1][0] = r[1];
                bl[2 * p][1] = r[2]; bl[2 * p + 1][1] = r[3];
            }
#pragma unroll
            for (int mi = 0; mi < 2; mi++)
#pragma unroll
                for (int nj = 0; nj < 8; nj++)
                    mma_bf16(d[mi][nj], ah[mi], bh[nj][0], bh[nj][1]);
#pragma unroll
            for (int mi = 0; mi < 2; mi++)
#pragma unroll
                for (int nj = 0; nj < 8; nj++)
                    mma_bf16(d[mi][nj], ah[mi], bl[nj][0], bl[nj][1]);
#pragma unroll
            for (int mi = 0; mi < 2; mi++)
#pragma unroll
                for (int nj = 0; nj < 8; nj++)
                    mma_bf16(d[mi][nj], al[mi], bh[nj][0], bh[nj][1]);
        }
    }

    // Epilogue: DEFAULT stores — keep cur resident in L2 for the scan phase.
#pragma unroll
    for (int nj = 0; nj < 8; nj++) {
        int cc = n0 + wn * 64 + nj * 8 + 2 * t;
        float2 bv = *(const float2*)&bias[cc];
#pragma unroll
        for (int mi = 0; mi < 2; mi++) {
            int r0 = m0 + wm * 32 + mi * 16 + g;
            float2 o0 = {d[mi][nj][0] + bv.x, d[mi][nj][1] + bv.y};
            float2 o1 = {d[mi][nj][2] + bv.x, d[mi][nj][3] + bv.y};
            *(float2*)&C[(size_t)r0 * OUT_DIM + cc]       = o0;
            *(float2*)&C[(size_t)(r0 + 8) * OUT_DIM + cc] = o1;
        }
    }
}

// ================= Parallel scan, stage 1: chunk-local EMA sums ==============
// 128 threads x 4 neurons (float4); default-policy loads (L2 reuse of cur).
__global__ __launch_bounds__(128)
void scan_s1_kernel(const float* __restrict__ decay, int T, int NCH) {
    const int bc = blockIdx.x;
    const int b  = bc / NCH;
    const int ch = bc % NCH;
    const int o4 = threadIdx.x * 4;
    if (ch == 0 && threadIdx.x == 0) g_flag[b] = 0;

    const float4 dd = *(const float4*)&decay[o4];
    const float4 om = {1.f - dd.x, 1.f - dd.y, 1.f - dd.z, 1.f - dd.w};
    const int t0 = ch * CH;
    const int len = min(T - t0, CH);
    const float* curB = g_cur + ((size_t)b * T + t0) * OUT_DIM + o4;

    const float4 zero4 = {0.f, 0.f, 0.f, 0.f};
    float4 c[4];
#pragma unroll
    for (int i = 0; i < 4; i++)
        c[i] = (i < len) ? *(const float4*)(curB + (size_t)i * OUT_DIM) : zero4;

    float4 s = zero4;
    int t = 0;
#pragma unroll 1
    for (; t + 4 <= len; t += 4) {
        float4 n[4];
#pragma unroll
        for (int u = 0; u < 4; u++)
            n[u] = (t + 4 + u < len)
                 ? *(const float4*)(curB + (size_t)(t + 4 + u) * OUT_DIM) : zero4;
#pragma unroll
        for (int u = 0; u < 4; u++) {
            s.x = dd.x * s.x + om.x * c[u].x;
            s.y = dd.y * s.y + om.y * c[u].y;
            s.z = dd.z * s.z + om.z * c[u].z;
            s.w = dd.w * s.w + om.w * c[u].w;
        }
#pragma unroll
        for (int u = 0; u < 4; u++) c[u] = n[u];
    }
#pragma unroll 1
    for (int u = 0; t < len; t++, u++) {
        s.x = dd.x * s.x + om.x * c[u].x;
        s.y = dd.y * s.y + om.y * c[u].y;
        s.z = dd.z * s.z + om.z * c[u].z;
        s.w = dd.w * s.w + om.w * c[u].w;
    }

    *(float4*)&g_csum[(size_t)bc * OUT_DIM + o4] = s;
}

// ================= stage 3: boundary combine + expand + flag ================
// 128 threads x 4 neurons; boundary recomputed inline from csum (L2-hot).
// All chunks before ch are full CH, so a single d^CH factor applies.
__global__ __launch_bounds__(128)
void scan_s3_kernel(const float* __restrict__ decay, int T, int NCH,
                    float* __restrict__ outputs,
                    float* __restrict__ statesV,
                    float* __restrict__ statesZ) {
    const int bc = blockIdx.x;
    const int b  = bc / NCH;
    const int ch = bc % NCH;
    const int o4 = threadIdx.x * 4;

    const float4 dd = *(const float4*)&decay[o4];
    const float4 om = {1.f - dd.x, 1.f - dd.y, 1.f - dd.z, 1.f - dd.w};
    const int t0 = ch * CH;
    const int len = min(T - t0, CH);

    const float* curB = g_cur + ((size_t)b * T + t0) * OUT_DIM + o4;
    float* outB = outputs + ((size_t)b * T + t0) * OUT_DIM + o4;
    float* svB  = statesV + ((size_t)b * (T + 1) + t0 + 1) * OUT_DIM + o4;
    float* szB  = statesZ + ((size_t)b * (T + 1) + t0 + 1) * OUT_DIM + o4;

    const float4 zero4 = {0.f, 0.f, 0.f, 0.f};
    if (ch == 0) {
        *(float4*)&statesV[((size_t)b * (T + 1)) * OUT_DIM + o4] = zero4;
        *(float4*)&statesZ[((size_t)b * (T + 1)) * OUT_DIM + o4] = zero4;
    }

    // boundary v at chunk start: vb = sum_{j<ch} dpCH^(ch-1-j) * csum[j]
    float4 v = zero4;
    if (ch > 0) {
        float4 dp = {1.f, 1.f, 1.f, 1.f};
#pragma unroll 1
        for (int i = 0; i < CH; i++) {
            dp.x *= dd.x; dp.y *= dd.y; dp.z *= dd.z; dp.w *= dd.w;
        }
#pragma unroll 1
        for (int j = 0; j < ch; j++) {
            float4 cs = *(const float4*)&g_csum[((size_t)b * NCH + j) * OUT_DIM + o4];
            v.x = dp.x * v.x + cs.x;
            v.y = dp.y * v.y + cs.y;
            v.z = dp.z * v.z + cs.z;
            v.w = dp.w * v.w + cs.w;
        }
    }

    float4 c[4];
#pragma unroll
    for (int i = 0; i < 4; i++)
        c[i] = (i < len) ? *(const float4*)(curB + (size_t)i * OUT_DIM) : zero4;

    bool spike = false;
    int t = 0;
#pragma unroll 1
    for (; t + 4 <= len; t += 4) {
        float4 n[4];
#pragma unroll
        for (int u = 0; u < 4; u++)
            n[u] = (t + 4 + u < len)
                 ? *(const float4*)(curB + (size_t)(t + 4 + u) * OUT_DIM) : zero4;
#pragma unroll
        for (int u = 0; u < 4; u++) {
            v.x = dd.x * v.x + om.x * c[u].x;
            v.y = dd.y * v.y + om.y * c[u].y;
            v.z = dd.z * v.z + om.z * c[u].z;
            v.w = dd.w * v.w + om.w * c[u].w;
            float4 z = {(v.x >= 1.f) ? 1.f : 0.f, (v.y >= 1.f) ? 1.f : 0.f,
                        (v.z >= 1.f) ? 1.f : 0.f, (v.w >= 1.f) ? 1.f : 0.f};
            spike |= (z.x + z.y + z.z + z.w) > 0.f;
            size_t off = (size_t)(t + u) * OUT_DIM;
            __stcs((float4*)(outB + off), z);
            __stcs((float4*)(svB + off), v);
            __stcs((float4*)(szB + off), z);
        }
#pragma unroll
        for (int u = 0; u < 4; u++) c[u] = n[u];
    }
#pragma unroll 1
    for (int u = 0; t < len; t++, u++) {
        v.x = dd.x * v.x + om.x * c[u].x;
        v.y = dd.y * v.y + om.y * c[u].y;
        v.z = dd.z * v.z + om.z * c[u].z;
        v.w = dd.w * v.w + om.w * c[u].w;
        float4 z = {(v.x >= 1.f) ? 1.f : 0.f, (v.y >= 1.f) ? 1.f : 0.f,
                    (v.z >= 1.f) ? 1.f : 0.f, (v.w >= 1.f) ? 1.f : 0.f};
        spike |= (z.x + z.y + z.z + z.w) > 0.f;
        size_t off = (size_t)t * OUT_DIM;
        __stcs((float4*)(outB + off), z);
        __stcs((float4*)(svB + off), v);
        __stcs((float4*)(szB + off), z);
    }
    if (__syncthreads_or(spike)) {
        if (threadIdx.x == 0) atomicOr(&g_flag[b], 1);
    }
}

// ================= stage 4: exact sequential fallback (flagged only) ========
__device__ __forceinline__ void lif_step(
    float c, float& v, float& z, int& anySpike,
    unsigned* smask, int o, int wid, int lane,
    float d, float omd,
    float* __restrict__ outB, float* __restrict__ svB, float* __restrict__ szB,
    int t)
{
    float soma = c;
    if (anySpike) {
#pragma unroll 1
        for (int w = 0; w < OUT_DIM / 32; w++) {
            unsigned m = smask[w];
            while (m) {
                int j = w * 32 + (__ffs(m) - 1);
                m &= (m - 1);
                soma += g_RT[(size_t)j * OUT_DIM + o];
            }
        }
    }
    v = d * (v * (1.f - z)) + omd * soma;
    z = (v >= 1.f) ? 1.f : 0.f;
    outB[(size_t)t * OUT_DIM + o]      = z;
    svB[(size_t)(t + 1) * OUT_DIM + o] = v;
    szB[(size_t)(t + 1) * OUT_DIM + o] = z;
    unsigned bal = __ballot_sync(0xffffffffu, z > 0.f);
    anySpike = __syncthreads_count(z > 0.f);
    if (anySpike) {
        if (lane == 0) smask[wid] = bal;
        __syncthreads();
    }
}

__global__ __launch_bounds__(OUT_DIM, 1)
void scan_s4_kernel(const float* __restrict__ decay,
                    float* __restrict__ outputs,
                    float* __restrict__ statesV,
                    float* __restrict__ statesZ,
                    int T) {
    const int b = blockIdx.x;
    if (g_flag[b] == 0) return;
    const int o = threadIdx.x;
    const int wid = o >> 5, lane = o & 31;

    __shared__ unsigned smask[OUT_DIM / 32];
    if (o < OUT_DIM / 32) smask[o] = 0u;

    const float d   = decay[o];
    const float omd = 1.f - d;

    const float* curB = g_cur + (size_t)b * T * OUT_DIM;
    float* outB = outputs + (size_t)b * T * OUT_DIM;
    float* svB  = statesV + (size_t)b * (T + 1) * OUT_DIM;
    float* szB  = statesZ + (size_t)b * (T + 1) * OUT_DIM;

    svB[o] = 0.f;
    szB[o] = 0.f;

    float v = 0.f, z = 0.f;
    int anySpike = 0;
    __syncthreads();

    float c0 = 0.f, c1 = 0.f, c2 = 0.f, c3 = 0.f;
    if (T > 0) c0 = curB[o];
    if (T > 1) c1 = curB[(size_t)OUT_DIM + o];
    if (T > 2) c2 = curB[(size_t)2 * OUT_DIM + o];
    if (T > 3) c3 = curB[(size_t)3 * OUT_DIM + o];

    int t = 0;
#pragma unroll 1
    for (; t + 3 < T; t += 4) {
        float n0 = (t + 4 < T) ? curB[(size_t)(t + 4) * OUT_DIM + o] : 0.f;
        lif_step(c0, v, z, anySpike, smask, o, wid, lane, d, omd, outB, svB, szB, t);
        float n1 = (t + 5 < T) ? curB[(size_t)(t + 5) * OUT_DIM + o] : 0.f;
        lif_step(c1, v, z, anySpike, smask, o, wid, lane, d, omd, outB, svB, szB, t + 1);
        float n2 = (t + 6 < T) ? curB[(size_t)(t + 6) * OUT_DIM + o] : 0.f;
        lif_step(c2, v, z, anySpike, smask, o, wid, lane, d, omd, outB, svB, szB, t + 2);
        float n3 = (t + 7 < T) ? curB[(size_t)(t + 7) * OUT_DIM + o] : 0.f;
        lif_step(c3, v, z, anySpike, smask, o, wid, lane, d, omd, outB, svB, szB, t + 3);
        c0 = n0; c1 = n1; c2 = n2; c3 = n3;
    }
    if (t < T) { lif_step(c0, v, z, anySpike, smask, o, wid, lane, d, omd, outB, svB, szB, t); t++; }
    if (t < T) { lif_step(c1, v, z, anySpike, smask, o, wid, lane, d, omd, outB, svB, szB, t); t++; }
    if (t < T) { lif_step(c2, v, z, anySpike, smask, o, wid, lane, d, omd, outB, svB, szB, t); t++; }
}

// ---------------------------------------------------------------------------
extern "C" void kernel_launch(void* const* d_in, const int* in_sizes, int n_in,
                              void* d_out, int out_size) {
    const float* x      = (const float*)d_in[0];  // [B, T, IN]
    const float* weight = (const float*)d_in[1];  // [OUT, IN]
    const float* bias   = (const float*)d_in[2];  // [OUT]
    const float* recur  = (const float*)d_in[3];  // [OUT, OUT]
    const float* decay  = (const float*)d_in[4];  // [OUT]

    const int OUT = in_sizes[2];                         // 512
    const int IN  = in_sizes[1] / OUT;                   // 512
    const long long M = (long long)in_sizes[0] / IN;     // B*T
    const long long B = (((long long)out_size / OUT) - 3 * M) / 2;
    const int T = (int)(M / B);
    const int NCH = (T + CH - 1) / CH;                   // 16 for T=1000

    float* outputs = (float*)d_out;                        // [B,T,OUT]
    float* statesV = outputs + (size_t)B * T * OUT;        // [B,T+1,OUT]
    float* statesZ = statesV + (size_t)B * (T + 1) * OUT;  // [B,T+1,OUT]

    float* cur;
    cudaGetSymbolAddress((void**)&cur, g_cur);

    convert_w_kernel<<<(OUT * IN / 4) / 256, 256>>>(weight);
    {
        dim3 grid(OUT / 32, OUT / 32), block(32, 32);
        transpose512_kernel<<<grid, block>>>(recur);
    }

    cudaFuncSetAttribute(gemm_hmma_kernel,
                         cudaFuncAttributeMaxDynamicSharedMemorySize, SMEM_GEMM);
    {
        dim3 grid((unsigned)(M / 128), OUT / 128);
        gemm_hmma_kernel<<<grid, 256, SMEM_GEMM>>>(x, bias, cur);
    }

    scan_s1_kernel<<<(unsigned)(B * NCH), 128>>>(decay, T, NCH);
    scan_s3_kernel<<<(unsigned)(B * NCH), 128>>>(decay, T, NCH,
                                                 outputs, statesV, statesZ);
    scan_s4_kernel<<<(unsigned)B, OUT>>>(decay, outputs, statesV, statesZ, T);
}